// round 2
// baseline (speedup 1.0000x reference)
#include <cuda_runtime.h>

#define QLEN 2048
#define BSZ 2
#define NH 12
#define DH 64
#define DM 768
#define NEGINF (-1e30f)
#define ATTN_SCALE 0.125f   // 1/sqrt(64)

// ---------------- scratch (static device allocations; no cudaMalloc allowed) ----
__device__ float g_Q[BSZ * NH * QLEN * DH];     // [b][n][i][d]
__device__ float g_K[BSZ * NH * QLEN * DH];
__device__ float g_V[BSZ * NH * QLEN * DH];
__device__ float g_att[QLEN * BSZ * DM];        // attn_vec, row r = i*BSZ+b
__device__ float g_res[QLEN * BSZ * DM];        // w + attn_out

// ================= Kernel 1: QKV GEMM ==========================================
// C[r,h] = sum_k w[r,k] * qkv_w[h,k]; scatter into g_Q / g_K / g_V.
// 64x64 tile per block, BK=16, 256 threads, 4x4 microtile per thread.
__global__ void __launch_bounds__(256) qkv_gemm_kernel(const float* __restrict__ A,
                                                       const float* __restrict__ B) {
    __shared__ float As[16][65];   // [k][m] transposed
    __shared__ float Bs[16][65];
    const int rb = blockIdx.x * 64;
    const int cb = blockIdx.y * 64;
    const int tid = threadIdx.x;
    const int tx = tid & 15, ty = tid >> 4;
    const int iloc = ty * 4, jloc = tx * 4;

    float acc[4][4] = {};
    for (int k0 = 0; k0 < DM; k0 += 16) {
        for (int e = tid; e < 1024; e += 256) {
            const int kk = e & 15, m = e >> 4;
            As[kk][m] = A[(rb + m) * DM + k0 + kk];
            Bs[kk][m] = B[(cb + m) * DM + k0 + kk];
        }
        __syncthreads();
#pragma unroll
        for (int kk = 0; kk < 16; kk++) {
            float qv[4], kv[4];
#pragma unroll
            for (int u = 0; u < 4; u++) qv[u] = As[kk][iloc + u];
#pragma unroll
            for (int u = 0; u < 4; u++) kv[u] = Bs[kk][jloc + u];
#pragma unroll
            for (int a = 0; a < 4; a++)
#pragma unroll
                for (int c = 0; c < 4; c++) acc[a][c] += qv[a] * kv[c];
        }
        __syncthreads();
    }
    // scatter into Q/K/V with [b][n][i][d] layout
#pragma unroll
    for (int a = 0; a < 4; a++) {
        const int r = rb + iloc + a;
        const int i = r >> 1, b = r & 1;
#pragma unroll
        for (int c = 0; c < 4; c++) {
            const int h = cb + jloc + c;
            const int sel = h / DM;          // 0=q 1=k 2=v (tile cols never straddle)
            const int rem = h - sel * DM;
            const int n = rem >> 6, d = rem & 63;
            float* dst = (sel == 0) ? g_Q : (sel == 1) ? g_K : g_V;
            dst[((b * NH + n) * QLEN + i) * DH + d] = acc[a][c];
        }
    }
}

// ================= Kernel 2: fused rel-attention (flash) =======================
// Per (b, n, 64-query-tile). S[i,j] = SCALE*( q_i·k_j + rwb_n·k_j
//                                            + q_i·r_emb[2047-(i-j),n] + r_bias[2047-(i-j),n] )
// for j<=i, online softmax, O = P V. attn_vec -> g_att[(i*BSZ+b)*DM + n*64 + d].
#define SMEM_FLOATS (64*65*3 + 128*65 + 128 + 64 + 64)
__global__ void __launch_bounds__(256, 2) attn_kernel(const float* __restrict__ r_emb,
                                                      const float* __restrict__ r_w_bias,
                                                      const float* __restrict__ r_bias) {
    extern __shared__ float sm[];
    float* Qs = sm;                 // 64*65
    float* Ks = Qs + 64 * 65;       // 64*65
    float* Vs = Ks + 64 * 65;       // 64*65
    float* Rs = Vs + 64 * 65;       // 128*65  (reused as Ps[64*65] in PV phase)
    float* Rb = Rs + 128 * 65;      // 128
    float* Bk = Rb + 128;           // 64
    float* Bw = Bk + 64;            // 64 (r_w_bias row for this head)

    const int bn = blockIdx.y;
    const int b = bn / NH, n = bn % NH;
    const int i0 = blockIdx.x * 64;
    const int tid = threadIdx.x;
    const int tx = tid & 15, ty = tid >> 4;
    const int iloc = ty * 4, jloc = tx * 4;
    const int rbase = 63 + jloc - iloc;    // Rs row for cell (0,0); cell (a,c) -> rbase + c - a

    // load Q tile
    const float* Qg = g_Q + ((b * NH + n) * QLEN + i0) * DH;
    for (int e = tid; e < 64 * 16; e += 256) {
        const int r = e >> 4, c4 = e & 15;
        float4 v = ((const float4*)(Qg + r * DH))[c4];
        float* p = &Qs[r * 65 + c4 * 4];
        p[0] = v.x; p[1] = v.y; p[2] = v.z; p[3] = v.w;
    }
    if (tid < 64) Bw[tid] = r_w_bias[n * DH + tid];

    float mi[4], li[4], Oacc[4][4];
#pragma unroll
    for (int a = 0; a < 4; a++) {
        mi[a] = NEGINF; li[a] = 0.f;
#pragma unroll
        for (int c = 0; c < 4; c++) Oacc[a][c] = 0.f;
    }

    const int njt = i0 / 64 + 1;   // causal: key tiles 0..i0/64
    for (int jt = 0; jt < njt; jt++) {
        const int j0 = jt * 64;
        __syncthreads();   // previous iter done reading smem (also covers Q load, Bw)

        const float* Kg = g_K + ((b * NH + n) * QLEN + j0) * DH;
        const float* Vg = g_V + ((b * NH + n) * QLEN + j0) * DH;
        for (int e = tid; e < 64 * 16; e += 256) {
            const int r = e >> 4, c4 = e & 15;
            float4 kv4 = ((const float4*)(Kg + r * DH))[c4];
            float* pk = &Ks[r * 65 + c4 * 4];
            pk[0] = kv4.x; pk[1] = kv4.y; pk[2] = kv4.z; pk[3] = kv4.w;
            float4 vv4 = ((const float4*)(Vg + r * DH))[c4];
            float* pv = &Vs[r * 65 + c4 * 4];
            pv[0] = vv4.x; pv[1] = vv4.y; pv[2] = vv4.z; pv[3] = vv4.w;
        }
        const int m0 = (QLEN - 1) - (i0 + 63) + j0;    // >= 0 always
        for (int e = tid; e < 128 * 16; e += 256) {
            const int rr = e >> 4, c4 = e & 15;
            const int m = m0 + rr;
            float4 rv4 = make_float4(0.f, 0.f, 0.f, 0.f);
            if (rr < 127 && m < QLEN)
                rv4 = ((const float4*)(r_emb + (m * NH + n) * DH))[c4];
            float* pr = &Rs[rr * 65 + c4 * 4];
            pr[0] = rv4.x; pr[1] = rv4.y; pr[2] = rv4.z; pr[3] = rv4.w;
        }
        if (tid < 128) {
            const int m = m0 + tid;
            Rb[tid] = (tid < 127 && m < QLEN) ? r_bias[m * NH + n] : 0.f;
        }
        __syncthreads();
        if (tid < 64) {      // bk[j] = r_w_bias_n · k_j
            float s = 0.f;
#pragma unroll
            for (int d = 0; d < 64; d++) s += Bw[d] * Ks[tid * 65 + d];
            Bk[tid] = s;
        }
        __syncthreads();

        // ---- S = q·k + q·r (banded) ----
        float acc[4][4] = {};
#pragma unroll 4
        for (int kk = 0; kk < 64; kk++) {
            float qv[4], kv[4], rv[7];
#pragma unroll
            for (int u = 0; u < 4; u++) qv[u] = Qs[(iloc + u) * 65 + kk];
#pragma unroll
            for (int u = 0; u < 4; u++) kv[u] = Ks[(jloc + u) * 65 + kk];
#pragma unroll
            for (int u = 0; u < 7; u++) rv[u] = Rs[(rbase - 3 + u) * 65 + kk];
#pragma unroll
            for (int a = 0; a < 4; a++)
#pragma unroll
                for (int c = 0; c < 4; c++)
                    acc[a][c] += qv[a] * (kv[c] + rv[c - a + 3]);
        }
        // biases + scale + causal mask
#pragma unroll
        for (int a = 0; a < 4; a++) {
            const int gi = i0 + iloc + a;
#pragma unroll
            for (int c = 0; c < 4; c++) {
                const int gj = j0 + jloc + c;
                float s = (acc[a][c] + Bk[jloc + c] + Rb[rbase + c - a]) * ATTN_SCALE;
                acc[a][c] = (gj <= gi) ? s : NEGINF;
            }
        }
        // online softmax update
        float rmax[4], rsum[4];
#pragma unroll
        for (int a = 0; a < 4; a++) {
            float m4 = fmaxf(fmaxf(acc[a][0], acc[a][1]), fmaxf(acc[a][2], acc[a][3]));
#pragma unroll
            for (int off = 8; off > 0; off >>= 1)
                m4 = fmaxf(m4, __shfl_xor_sync(0xffffffffu, m4, off, 32));
            rmax[a] = m4;
        }
#pragma unroll
        for (int a = 0; a < 4; a++) {
            const float mnew = fmaxf(mi[a], rmax[a]);
            const float csc = __expf(mi[a] - mnew);   // mi=-1e30 first iter -> 0
            mi[a] = mnew;
            float rs = 0.f;
#pragma unroll
            for (int c = 0; c < 4; c++) {
                const float p = __expf(acc[a][c] - mnew);   // masked -> exp(-1e30) = 0
                acc[a][c] = p;
                rs += p;
            }
            rsum[a] = rs;
            li[a] = li[a] * csc;
#pragma unroll
            for (int c = 0; c < 4; c++) Oacc[a][c] *= csc;
        }
#pragma unroll
        for (int a = 0; a < 4; a++) {
            float rs = rsum[a];
#pragma unroll
            for (int off = 8; off > 0; off >>= 1)
                rs += __shfl_xor_sync(0xffffffffu, rs, off, 32);
            li[a] += rs;
        }

        __syncthreads();   // all threads finished reading Rs -> safe to overwrite as Ps
        float* Ps = Rs;
#pragma unroll
        for (int a = 0; a < 4; a++)
#pragma unroll
            for (int c = 0; c < 4; c++)
                Ps[(iloc + a) * 65 + jloc + c] = acc[a][c];
        __syncthreads();

        // ---- O += P @ V ----
#pragma unroll 4
        for (int kk = 0; kk < 64; kk++) {
            float pv[4], vv[4];
#pragma unroll
            for (int u = 0; u < 4; u++) pv[u] = Ps[(iloc + u) * 65 + kk];
#pragma unroll
            for (int u = 0; u < 4; u++) vv[u] = Vs[kk * 65 + jloc + u];
#pragma unroll
            for (int a = 0; a < 4; a++)
#pragma unroll
                for (int c = 0; c < 4; c++) Oacc[a][c] += pv[a] * vv[c];
        }
    }

    // epilogue: normalize + write attn_vec
#pragma unroll
    for (int a = 0; a < 4; a++) {
        const int gi = i0 + iloc + a;
        const float inv = 1.f / li[a];
#pragma unroll
        for (int c = 0; c < 4; c++)
            g_att[(gi * BSZ + b) * DM + n * DH + jloc + c] = Oacc[a][c] * inv;
    }
}

// ================= Kernel 3: O projection + residual ==========================
// g_res[r,m] = sum_h g_att[r,h]*o_w[m,h] + w[r,m]
__global__ void __launch_bounds__(256) oproj_kernel(const float* __restrict__ B,
                                                    const float* __restrict__ W) {
    __shared__ float As[16][65];
    __shared__ float Bs[16][65];
    const int rb = blockIdx.x * 64;
    const int cb = blockIdx.y * 64;
    const int tid = threadIdx.x;
    const int tx = tid & 15, ty = tid >> 4;
    const int iloc = ty * 4, jloc = tx * 4;

    float acc[4][4] = {};
    for (int k0 = 0; k0 < DM; k0 += 16) {
        for (int e = tid; e < 1024; e += 256) {
            const int kk = e & 15, m = e >> 4;
            As[kk][m] = g_att[(rb + m) * DM + k0 + kk];
            Bs[kk][m] = B[(cb + m) * DM + k0 + kk];
        }
        __syncthreads();
#pragma unroll
        for (int kk = 0; kk < 16; kk++) {
            float qv[4], kv[4];
#pragma unroll
            for (int u = 0; u < 4; u++) qv[u] = As[kk][iloc + u];
#pragma unroll
            for (int u = 0; u < 4; u++) kv[u] = Bs[kk][jloc + u];
#pragma unroll
            for (int a = 0; a < 4; a++)
#pragma unroll
                for (int c = 0; c < 4; c++) acc[a][c] += qv[a] * kv[c];
        }
        __syncthreads();
    }
#pragma unroll
    for (int a = 0; a < 4; a++) {
        const int r = rb + iloc + a;
#pragma unroll
        for (int c = 0; c < 4; c++) {
            const int m = cb + jloc + c;
            g_res[r * DM + m] = acc[a][c] + W[r * DM + m];
        }
    }
}

// ================= Kernel 4: LayerNorm ========================================
__device__ __forceinline__ float block_sum(float v, float* red) {
#pragma unroll
    for (int o = 16; o > 0; o >>= 1) v += __shfl_xor_sync(0xffffffffu, v, o);
    const int w = threadIdx.x >> 5;
    if ((threadIdx.x & 31) == 0) red[w] = v;
    __syncthreads();
    if (threadIdx.x < 32) {
        float t = (threadIdx.x < 8) ? red[threadIdx.x] : 0.f;
#pragma unroll
        for (int o = 4; o > 0; o >>= 1) t += __shfl_xor_sync(0xffffffffu, t, o);
        if (threadIdx.x == 0) red[0] = t;
    }
    __syncthreads();
    const float r = red[0];
    __syncthreads();
    return r;
}

__global__ void __launch_bounds__(256) ln_kernel(const float* __restrict__ gamma,
                                                 const float* __restrict__ beta,
                                                 float* __restrict__ out) {
    __shared__ float red[8];
    const int r = blockIdx.x;
    const float* x = g_res + (size_t)r * DM;
    const int tid = threadIdx.x;
    float v[3];
#pragma unroll
    for (int u = 0; u < 3; u++) v[u] = x[tid + u * 256];
    const float total = block_sum(v[0] + v[1] + v[2], red);
    const float mu = total * (1.f / DM);
    float sq = 0.f;
#pragma unroll
    for (int u = 0; u < 3; u++) { const float d = v[u] - mu; sq += d * d; }
    const float var = block_sum(sq, red) * (1.f / DM);
    const float inv = rsqrtf(var + 1e-5f);
#pragma unroll
    for (int u = 0; u < 3; u++) {
        const int c = tid + u * 256;
        out[(size_t)r * DM + c] = (v[u] - mu) * inv * gamma[c] + beta[c];
    }
}

// ================= launch =====================================================
extern "C" void kernel_launch(void* const* d_in, const int* in_sizes, int n_in,
                              void* d_out, int out_size) {
    const float* w        = (const float*)d_in[0];
    const float* r_emb    = (const float*)d_in[1];
    const float* r_w_bias = (const float*)d_in[2];
    const float* r_bias   = (const float*)d_in[3];
    const float* qkv_w    = (const float*)d_in[4];
    const float* o_w      = (const float*)d_in[5];
    const float* ln_g     = (const float*)d_in[6];
    const float* ln_b     = (const float*)d_in[7];
    // d_in[8] = attn_mask (causal triu, k=1) — applied analytically, not read.
    float* out = (float*)d_out;

    qkv_gemm_kernel<<<dim3(64, 36), 256>>>(w, qkv_w);

    const int smem_bytes = SMEM_FLOATS * (int)sizeof(float);   // ~84 KB
    (void)cudaFuncSetAttribute(attn_kernel, cudaFuncAttributeMaxDynamicSharedMemorySize, smem_bytes);
    attn_kernel<<<dim3(QLEN / 64, BSZ * NH), 256, smem_bytes>>>(r_emb, r_w_bias, r_bias);

    oproj_kernel<<<dim3(64, 12), 256>>>(o_w, w);
    ln_kernel<<<QLEN * BSZ, 256>>>(ln_g, ln_b, out);
}

// round 4
// speedup vs baseline: 1.4400x; 1.4400x over previous
#include <cuda_runtime.h>
#include <cstdint>

#define QLEN 2048
#define BSZ 2
#define NH 12
#define DH 64
#define DM 768
#define NEGINF (-1e30f)
#define ATTN_SCALE 0.125f   // 1/sqrt(64)

// ---------------- scratch (static device allocations; no cudaMalloc allowed) ----
__device__ float g_Q[BSZ * NH * QLEN * DH];     // [b][n][i][d]
__device__ float g_K[BSZ * NH * QLEN * DH];
__device__ float g_V[BSZ * NH * QLEN * DH];
__device__ float g_att[QLEN * BSZ * DM];        // attn_vec, row r = i*BSZ+b
__device__ float g_res[QLEN * BSZ * DM];        // w + attn_out

__device__ __forceinline__ uint32_t f2tf32(float x) {
    uint32_t u;
    asm("cvt.rna.tf32.f32 %0, %1;" : "=r"(u) : "f"(x));
    return u;
}

// ================= mma.sync tf32 GEMM ==========================================
// C[r, c] = sum_k A[r, k] * B[c, k]   (both K-major, .row.col mma)
// Block 128x128, BK=32, 8 warps (4 along M x 2 along N), warp tile 32x64.
// MODE 0: scatter into g_Q/g_K/g_V.   MODE 1: += W residual, write g_res.
#define BM 128
#define BN 128
#define BKC 32
#define LDP (BKC + 4)

#define MMA_TF32(d, a, b)                                                          \
    asm volatile("mma.sync.aligned.m16n8k8.row.col.f32.tf32.tf32.f32 "             \
                 "{%0,%1,%2,%3}, {%4,%5,%6,%7}, {%8,%9}, {%0,%1,%2,%3};"           \
                 : "+f"((d)[0]), "+f"((d)[1]), "+f"((d)[2]), "+f"((d)[3])          \
                 : "r"((a)[0]), "r"((a)[1]), "r"((a)[2]), "r"((a)[3]),             \
                   "r"((b)[0]), "r"((b)[1]))

template <int MODE>
__global__ void __launch_bounds__(256) mma_gemm_kernel(const float* __restrict__ A,
                                                       const float* __restrict__ B,
                                                       const float* __restrict__ W,
                                                       int kdim) {
    __shared__ float As[BM][LDP];
    __shared__ float Bs[BN][LDP];

    const int tid = threadIdx.x;
    const int wid = tid >> 5, lane = tid & 31;
    const int wm = wid & 3;          // warp row: 4 x 32
    const int wn = wid >> 2;         // warp col: 2 x 64
    const int rb = blockIdx.x * BM;
    const int cb = blockIdx.y * BN;
    const int lq = lane >> 2;        // lane / 4  (0..7)
    const int lr = lane & 3;         // lane % 4  (0..3)

    float acc[2][8][4];
#pragma unroll
    for (int mt = 0; mt < 2; mt++)
#pragma unroll
        for (int nt = 0; nt < 8; nt++)
#pragma unroll
            for (int u = 0; u < 4; u++) acc[mt][nt][u] = 0.f;

    const int nchunk = kdim / BKC;
    for (int c = 0; c < nchunk; c++) {
        const int k0 = c * BKC;
        // fill smem tiles (convert to tf32 bit pattern with round-to-nearest)
        for (int e = tid; e < BM * BKC / 4; e += 256) {
            const int row = e >> 3, c4 = e & 7;
            float4 av = *(const float4*)(A + (size_t)(rb + row) * kdim + k0 + c4 * 4);
            float* pa = &As[row][c4 * 4];
            pa[0] = __uint_as_float(f2tf32(av.x));
            pa[1] = __uint_as_float(f2tf32(av.y));
            pa[2] = __uint_as_float(f2tf32(av.z));
            pa[3] = __uint_as_float(f2tf32(av.w));
            float4 bv = *(const float4*)(B + (size_t)(cb + row) * kdim + k0 + c4 * 4);
            float* pb = &Bs[row][c4 * 4];
            pb[0] = __uint_as_float(f2tf32(bv.x));
            pb[1] = __uint_as_float(f2tf32(bv.y));
            pb[2] = __uint_as_float(f2tf32(bv.z));
            pb[3] = __uint_as_float(f2tf32(bv.w));
        }
        __syncthreads();
#pragma unroll
        for (int kk = 0; kk < BKC / 8; kk++) {
            const int k = kk * 8;
            uint32_t af[2][4];
#pragma unroll
            for (int mt = 0; mt < 2; mt++) {
                const int ar = wm * 32 + mt * 16 + lq;
                af[mt][0] = __float_as_uint(As[ar][k + lr]);
                af[mt][1] = __float_as_uint(As[ar + 8][k + lr]);
                af[mt][2] = __float_as_uint(As[ar][k + 4 + lr]);
                af[mt][3] = __float_as_uint(As[ar + 8][k + 4 + lr]);
            }
            uint32_t bf[8][2];
#pragma unroll
            for (int nt = 0; nt < 8; nt++) {
                const int bc = wn * 64 + nt * 8 + lq;
                bf[nt][0] = __float_as_uint(Bs[bc][k + lr]);
                bf[nt][1] = __float_as_uint(Bs[bc][k + 4 + lr]);
            }
#pragma unroll
            for (int mt = 0; mt < 2; mt++)
#pragma unroll
                for (int nt = 0; nt < 8; nt++)
                    MMA_TF32(acc[mt][nt], af[mt], bf[nt]);
        }
        __syncthreads();
    }

    // ---- epilogue: each thread owns 2 rows x 2 cols per (mt, nt) fragment ----
#pragma unroll
    for (int mt = 0; mt < 2; mt++) {
#pragma unroll
        for (int half = 0; half < 2; half++) {
            const int r = rb + wm * 32 + mt * 16 + lq + half * 8;
#pragma unroll
            for (int nt = 0; nt < 8; nt++) {
                const int h = cb + wn * 64 + nt * 8 + lr * 2;
                const float v0 = acc[mt][nt][half * 2 + 0];
                const float v1 = acc[mt][nt][half * 2 + 1];
                if (MODE == 0) {
                    const int i = r >> 1, b = r & 1;
                    const int sel = h / DM;
                    const int rem = h - sel * DM;
                    const int n = rem >> 6, d0 = rem & 63;
                    float* dst = (sel == 0) ? g_Q : (sel == 1) ? g_K : g_V;
                    float2* p = (float2*)(dst + ((size_t)(b * NH + n) * QLEN + i) * DH + d0);
                    *p = make_float2(v0, v1);
                } else {
                    const float2 wv = *(const float2*)(W + (size_t)r * DM + h);
                    *(float2*)(g_res + (size_t)r * DM + h) =
                        make_float2(v0 + wv.x, v1 + wv.y);
                }
            }
        }
    }
}

// ================= Kernel 2: fused rel-attention (flash, SIMT fp32) ============
#define SMEM_FLOATS (64*65*3 + 128*65 + 128 + 64 + 64)
__global__ void __launch_bounds__(256, 2) attn_kernel(const float* __restrict__ r_emb,
                                                      const float* __restrict__ r_w_bias,
                                                      const float* __restrict__ r_bias) {
    extern __shared__ float smf[];
    float* Qs = smf;                // 64*65
    float* Ks = Qs + 64 * 65;       // 64*65
    float* Vs = Ks + 64 * 65;       // 64*65
    float* Rs = Vs + 64 * 65;       // 128*65  (reused as Ps[64*65] in PV phase)
    float* Rb = Rs + 128 * 65;      // 128
    float* Bk = Rb + 128;           // 64
    float* Bw = Bk + 64;            // 64

    const int bn = blockIdx.y;
    const int b = bn / NH, n = bn % NH;
    const int i0 = blockIdx.x * 64;
    const int tid = threadIdx.x;
    const int tx = tid & 15, ty = tid >> 4;
    const int iloc = ty * 4, jloc = tx * 4;
    const int rbase = 63 + jloc - iloc;

    const float* Qg = g_Q + ((b * NH + n) * QLEN + i0) * DH;
    for (int e = tid; e < 64 * 16; e += 256) {
        const int r = e >> 4, c4 = e & 15;
        float4 v = ((const float4*)(Qg + r * DH))[c4];
        float* p = &Qs[r * 65 + c4 * 4];
        p[0] = v.x; p[1] = v.y; p[2] = v.z; p[3] = v.w;
    }
    if (tid < 64) Bw[tid] = r_w_bias[n * DH + tid];

    float mi[4], li[4], Oacc[4][4];
#pragma unroll
    for (int a = 0; a < 4; a++) {
        mi[a] = NEGINF; li[a] = 0.f;
#pragma unroll
        for (int c = 0; c < 4; c++) Oacc[a][c] = 0.f;
    }

    const int njt = i0 / 64 + 1;
    for (int jt = 0; jt < njt; jt++) {
        const int j0 = jt * 64;
        __syncthreads();

        const float* Kg = g_K + ((b * NH + n) * QLEN + j0) * DH;
        const float* Vg = g_V + ((b * NH + n) * QLEN + j0) * DH;
        for (int e = tid; e < 64 * 16; e += 256) {
            const int r = e >> 4, c4 = e & 15;
            float4 kv4 = ((const float4*)(Kg + r * DH))[c4];
            float* pk = &Ks[r * 65 + c4 * 4];
            pk[0] = kv4.x; pk[1] = kv4.y; pk[2] = kv4.z; pk[3] = kv4.w;
            float4 vv4 = ((const float4*)(Vg + r * DH))[c4];
            float* pv = &Vs[r * 65 + c4 * 4];
            pv[0] = vv4.x; pv[1] = vv4.y; pv[2] = vv4.z; pv[3] = vv4.w;
        }
        const int m0 = (QLEN - 1) - (i0 + 63) + j0;
        for (int e = tid; e < 128 * 16; e += 256) {
            const int rr = e >> 4, c4 = e & 15;
            const int m = m0 + rr;
            float4 rv4 = make_float4(0.f, 0.f, 0.f, 0.f);
            if (rr < 127 && m < QLEN)
                rv4 = ((const float4*)(r_emb + (m * NH + n) * DH))[c4];
            float* pr = &Rs[rr * 65 + c4 * 4];
            pr[0] = rv4.x; pr[1] = rv4.y; pr[2] = rv4.z; pr[3] = rv4.w;
        }
        if (tid < 128) {
            const int m = m0 + tid;
            Rb[tid] = (tid < 127 && m < QLEN) ? r_bias[m * NH + n] : 0.f;
        }
        __syncthreads();
        if (tid < 64) {
            float s = 0.f;
#pragma unroll
            for (int d = 0; d < 64; d++) s += Bw[d] * Ks[tid * 65 + d];
            Bk[tid] = s;
        }
        __syncthreads();

        float acc[4][4] = {};
#pragma unroll 4
        for (int kk = 0; kk < 64; kk++) {
            float qv[4], kv[4], rv[7];
#pragma unroll
            for (int u = 0; u < 4; u++) qv[u] = Qs[(iloc + u) * 65 + kk];
#pragma unroll
            for (int u = 0; u < 4; u++) kv[u] = Ks[(jloc + u) * 65 + kk];
#pragma unroll
            for (int u = 0; u < 7; u++) rv[u] = Rs[(rbase - 3 + u) * 65 + kk];
#pragma unroll
            for (int a = 0; a < 4; a++)
#pragma unroll
                for (int c = 0; c < 4; c++)
                    acc[a][c] += qv[a] * (kv[c] + rv[c - a + 3]);
        }
#pragma unroll
        for (int a = 0; a < 4; a++) {
            const int gi = i0 + iloc + a;
#pragma unroll
            for (int c = 0; c < 4; c++) {
                const int gj = j0 + jloc + c;
                float s = (acc[a][c] + Bk[jloc + c] + Rb[rbase + c - a]) * ATTN_SCALE;
                acc[a][c] = (gj <= gi) ? s : NEGINF;
            }
        }
        float rmax[4], rsum[4];
#pragma unroll
        for (int a = 0; a < 4; a++) {
            float m4 = fmaxf(fmaxf(acc[a][0], acc[a][1]), fmaxf(acc[a][2], acc[a][3]));
#pragma unroll
            for (int off = 8; off > 0; off >>= 1)
                m4 = fmaxf(m4, __shfl_xor_sync(0xffffffffu, m4, off, 32));
            rmax[a] = m4;
        }
#pragma unroll
        for (int a = 0; a < 4; a++) {
            const float mnew = fmaxf(mi[a], rmax[a]);
            const float csc = __expf(mi[a] - mnew);
            mi[a] = mnew;
            float rs = 0.f;
#pragma unroll
            for (int c = 0; c < 4; c++) {
                const float p = __expf(acc[a][c] - mnew);
                acc[a][c] = p;
                rs += p;
            }
            rsum[a] = rs;
            li[a] = li[a] * csc;
#pragma unroll
            for (int c = 0; c < 4; c++) Oacc[a][c] *= csc;
        }
#pragma unroll
        for (int a = 0; a < 4; a++) {
            float rs = rsum[a];
#pragma unroll
            for (int off = 8; off > 0; off >>= 1)
                rs += __shfl_xor_sync(0xffffffffu, rs, off, 32);
            li[a] += rs;
        }

        __syncthreads();
        float* Ps = Rs;
#pragma unroll
        for (int a = 0; a < 4; a++)
#pragma unroll
            for (int c = 0; c < 4; c++)
                Ps[(iloc + a) * 65 + jloc + c] = acc[a][c];
        __syncthreads();

#pragma unroll 4
        for (int kk = 0; kk < 64; kk++) {
            float pv[4], vv[4];
#pragma unroll
            for (int u = 0; u < 4; u++) pv[u] = Ps[(iloc + u) * 65 + kk];
#pragma unroll
            for (int u = 0; u < 4; u++) vv[u] = Vs[kk * 65 + jloc + u];
#pragma unroll
            for (int a = 0; a < 4; a++)
#pragma unroll
                for (int c = 0; c < 4; c++) Oacc[a][c] += pv[a] * vv[c];
        }
    }

#pragma unroll
    for (int a = 0; a < 4; a++) {
        const int gi = i0 + iloc + a;
        const float inv = 1.f / li[a];
#pragma unroll
        for (int c = 0; c < 4; c++)
            g_att[(gi * BSZ + b) * DM + n * DH + jloc + c] = Oacc[a][c] * inv;
    }
}

// ================= Kernel 4: LayerNorm ========================================
__device__ __forceinline__ float block_sum(float v, float* red) {
#pragma unroll
    for (int o = 16; o > 0; o >>= 1) v += __shfl_xor_sync(0xffffffffu, v, o);
    const int w = threadIdx.x >> 5;
    if ((threadIdx.x & 31) == 0) red[w] = v;
    __syncthreads();
    if (threadIdx.x < 32) {
        float t = (threadIdx.x < 8) ? red[threadIdx.x] : 0.f;
#pragma unroll
        for (int o = 4; o > 0; o >>= 1) t += __shfl_xor_sync(0xffffffffu, t, o);
        if (threadIdx.x == 0) red[0] = t;
    }
    __syncthreads();
    const float r = red[0];
    __syncthreads();
    return r;
}

__global__ void __launch_bounds__(256) ln_kernel(const float* __restrict__ gamma,
                                                 const float* __restrict__ beta,
                                                 float* __restrict__ out) {
    __shared__ float red[8];
    const int r = blockIdx.x;
    const float* x = g_res + (size_t)r * DM;
    const int tid = threadIdx.x;
    float v[3];
#pragma unroll
    for (int u = 0; u < 3; u++) v[u] = x[tid + u * 256];
    const float total = block_sum(v[0] + v[1] + v[2], red);
    const float mu = total * (1.f / DM);
    float sq = 0.f;
#pragma unroll
    for (int u = 0; u < 3; u++) { const float d = v[u] - mu; sq += d * d; }
    const float var = block_sum(sq, red) * (1.f / DM);
    const float inv = rsqrtf(var + 1e-5f);
#pragma unroll
    for (int u = 0; u < 3; u++) {
        const int c = tid + u * 256;
        out[(size_t)r * DM + c] = (v[u] - mu) * inv * gamma[c] + beta[c];
    }
}

// ================= launch =====================================================
extern "C" void kernel_launch(void* const* d_in, const int* in_sizes, int n_in,
                              void* d_out, int out_size) {
    const float* w        = (const float*)d_in[0];
    const float* r_emb    = (const float*)d_in[1];
    const float* r_w_bias = (const float*)d_in[2];
    const float* r_bias   = (const float*)d_in[3];
    const float* qkv_w    = (const float*)d_in[4];
    const float* o_w      = (const float*)d_in[5];
    const float* ln_g     = (const float*)d_in[6];
    const float* ln_b     = (const float*)d_in[7];
    float* out = (float*)d_out;

    float* g_att_ptr = nullptr;
    cudaGetSymbolAddress((void**)&g_att_ptr, g_att);

    // QKV: C[4096 x 2304] = w[4096 x 768] * qkv_w[2304 x 768]^T  -> scatter Q/K/V
    mma_gemm_kernel<0><<<dim3(QLEN * BSZ / BM, 3 * DM / BN), 256>>>(w, qkv_w, nullptr, DM);

    const int smem_bytes = SMEM_FLOATS * (int)sizeof(float);   // ~84 KB
    (void)cudaFuncSetAttribute(attn_kernel, cudaFuncAttributeMaxDynamicSharedMemorySize, smem_bytes);
    attn_kernel<<<dim3(QLEN / 64, BSZ * NH), 256, smem_bytes>>>(r_emb, r_w_bias, r_bias);

    // O-proj: g_res[4096 x 768] = g_att * o_w^T + w
    mma_gemm_kernel<1><<<dim3(QLEN * BSZ / BM, DM / BN), 256>>>(g_att_ptr, o_w, w, DM);

    ln_kernel<<<QLEN * BSZ, 256>>>(ln_g, ln_b, out);
}

// round 5
// speedup vs baseline: 2.1473x; 1.4912x over previous
#include <cuda_runtime.h>
#include <cstdint>

#define QLEN 2048
#define BSZ 2
#define NH 12
#define DH 64
#define DM 768
#define NEGINF (-1e30f)
#define ATTN_SCALE 0.125f                 // 1/sqrt(64)
#define SCALE_L2E 0.1803368801111244f     // ATTN_SCALE * log2(e)

// ---------------- scratch (static device allocations; no cudaMalloc allowed) ----
__device__ float g_Q[BSZ * NH * QLEN * DH];     // [b][n][i][d]
__device__ float g_K[BSZ * NH * QLEN * DH];
__device__ float g_V[BSZ * NH * QLEN * DH];
__device__ float g_att[QLEN * BSZ * DM];        // attn_vec, row r = i*BSZ+b
__device__ float g_res[QLEN * BSZ * DM];        // w + attn_out

__device__ __forceinline__ uint32_t f2tf32(float x) {
    uint32_t u;
    asm("cvt.rna.tf32.f32 %0, %1;" : "=r"(u) : "f"(x));
    return u;
}

#define MMA_TF32(d, a, b)                                                          \
    asm volatile("mma.sync.aligned.m16n8k8.row.col.f32.tf32.tf32.f32 "             \
                 "{%0,%1,%2,%3}, {%4,%5,%6,%7}, {%8,%9}, {%0,%1,%2,%3};"           \
                 : "+f"((d)[0]), "+f"((d)[1]), "+f"((d)[2]), "+f"((d)[3])          \
                 : "r"((a)[0]), "r"((a)[1]), "r"((a)[2]), "r"((a)[3]),             \
                   "r"((b)[0]), "r"((b)[1]))

// fast 2^t for t <= 0 (clamped at -100); deg-4 Taylor in f*ln2, |f|<=0.5; rel err <= ~9e-5
__device__ __forceinline__ float exp2_poly(float t) {
    t = fmaxf(t, -100.f);
    const float r = rintf(t);
    const float y = (t - r) * 0.6931471805599453f;
    float p = 0.041666667f;
    p = p * y + 0.166666667f;
    p = p * y + 0.5f;
    p = p * y + 1.0f;
    p = p * y + 1.0f;
    const int ri = (int)r;
    return p * __int_as_float((ri + 127) << 23);
}

// ================= mma.sync tf32 projection GEMM (unchanged from R4) ===========
#define BM 128
#define BN 128
#define BKC 32
#define LDP (BKC + 4)

template <int MODE>
__global__ void __launch_bounds__(256) mma_gemm_kernel(const float* __restrict__ A,
                                                       const float* __restrict__ B,
                                                       const float* __restrict__ W,
                                                       int kdim) {
    __shared__ float As[BM][LDP];
    __shared__ float Bs[BN][LDP];

    const int tid = threadIdx.x;
    const int wid = tid >> 5, lane = tid & 31;
    const int wm = wid & 3;
    const int wn = wid >> 2;
    const int rb = blockIdx.x * BM;
    const int cb = blockIdx.y * BN;
    const int lq = lane >> 2;
    const int lr = lane & 3;

    float acc[2][8][4];
#pragma unroll
    for (int mt = 0; mt < 2; mt++)
#pragma unroll
        for (int nt = 0; nt < 8; nt++)
#pragma unroll
            for (int u = 0; u < 4; u++) acc[mt][nt][u] = 0.f;

    const int nchunk = kdim / BKC;
    for (int c = 0; c < nchunk; c++) {
        const int k0 = c * BKC;
        for (int e = tid; e < BM * BKC / 4; e += 256) {
            const int row = e >> 3, c4 = e & 7;
            float4 av = *(const float4*)(A + (size_t)(rb + row) * kdim + k0 + c4 * 4);
            float* pa = &As[row][c4 * 4];
            pa[0] = __uint_as_float(f2tf32(av.x));
            pa[1] = __uint_as_float(f2tf32(av.y));
            pa[2] = __uint_as_float(f2tf32(av.z));
            pa[3] = __uint_as_float(f2tf32(av.w));
            float4 bv = *(const float4*)(B + (size_t)(cb + row) * kdim + k0 + c4 * 4);
            float* pb = &Bs[row][c4 * 4];
            pb[0] = __uint_as_float(f2tf32(bv.x));
            pb[1] = __uint_as_float(f2tf32(bv.y));
            pb[2] = __uint_as_float(f2tf32(bv.z));
            pb[3] = __uint_as_float(f2tf32(bv.w));
        }
        __syncthreads();
#pragma unroll
        for (int kk = 0; kk < BKC / 8; kk++) {
            const int k = kk * 8;
            uint32_t af[2][4];
#pragma unroll
            for (int mt = 0; mt < 2; mt++) {
                const int ar = wm * 32 + mt * 16 + lq;
                af[mt][0] = __float_as_uint(As[ar][k + lr]);
                af[mt][1] = __float_as_uint(As[ar + 8][k + lr]);
                af[mt][2] = __float_as_uint(As[ar][k + 4 + lr]);
                af[mt][3] = __float_as_uint(As[ar + 8][k + 4 + lr]);
            }
            uint32_t bf[8][2];
#pragma unroll
            for (int nt = 0; nt < 8; nt++) {
                const int bc = wn * 64 + nt * 8 + lq;
                bf[nt][0] = __float_as_uint(Bs[bc][k + lr]);
                bf[nt][1] = __float_as_uint(Bs[bc][k + 4 + lr]);
            }
#pragma unroll
            for (int mt = 0; mt < 2; mt++)
#pragma unroll
                for (int nt = 0; nt < 8; nt++)
                    MMA_TF32(acc[mt][nt], af[mt], bf[nt]);
        }
        __syncthreads();
    }

#pragma unroll
    for (int mt = 0; mt < 2; mt++) {
#pragma unroll
        for (int half = 0; half < 2; half++) {
            const int r = rb + wm * 32 + mt * 16 + lq + half * 8;
#pragma unroll
            for (int nt = 0; nt < 8; nt++) {
                const int h = cb + wn * 64 + nt * 8 + lr * 2;
                const float v0 = acc[mt][nt][half * 2 + 0];
                const float v1 = acc[mt][nt][half * 2 + 1];
                if (MODE == 0) {
                    const int i = r >> 1, b = r & 1;
                    const int sel = h / DM;
                    const int rem = h - sel * DM;
                    const int n = rem >> 6, d0 = rem & 63;
                    float* dst = (sel == 0) ? g_Q : (sel == 1) ? g_K : g_V;
                    float2* p = (float2*)(dst + ((size_t)(b * NH + n) * QLEN + i) * DH + d0);
                    *p = make_float2(v0, v1);
                } else {
                    const float2 wv = *(const float2*)(W + (size_t)r * DM + h);
                    *(float2*)(g_res + (size_t)r * DM + h) =
                        make_float2(v0 + wv.x, v1 + wv.y);
                }
            }
        }
    }
}

// ================= Kernel 2: tensor-core flash rel-attention ===================
// Block = (b, n, 64-query tile). ST[64x192] = Q . [K(64); r_emb band(127)]^T via mma,
// band gathered during SIMT softmax (poly exp2), then P.V via mma.
#define LKR 68
#define LST 196
#define LPV 68
// smem float offsets
#define OF_KR   0
#define OF_VT   (OF_KR + 192 * LKR)          // 13056
#define OF_ST   (OF_VT + 64 * LPV)           // 17408
#define OF_P    (OF_ST + 64 * LST)           // 29952
#define OF_BW   (OF_P + 64 * LPV)            // 34304
#define OF_BK   (OF_BW + 64)
#define OF_RB   (OF_BK + 64)
#define OF_CSC  (OF_RB + 128)
#define OF_LI   (OF_CSC + 64)
#define ATTN_SMEM_FLOATS (OF_LI + 64)        // 34688 floats = 138752 B

__global__ void __launch_bounds__(256, 1) attn_kernel(const float* __restrict__ r_emb,
                                                      const float* __restrict__ r_w_bias,
                                                      const float* __restrict__ r_bias) {
    extern __shared__ float sm[];
    float* KRs = sm + OF_KR;
    float* Vt  = sm + OF_VT;
    float* STs = sm + OF_ST;
    float* Ps  = sm + OF_P;
    float* Bws = sm + OF_BW;
    float* Bks = sm + OF_BK;
    float* Rbs = sm + OF_RB;
    float* cscs = sm + OF_CSC;
    float* lis  = sm + OF_LI;

    const int bn = blockIdx.y;
    const int b = bn / NH, n = bn % NH;
    const int it = (gridDim.x - 1) - blockIdx.x;   // longest blocks first
    const int i0 = it * 64;
    const int tid = threadIdx.x;
    const int wid = tid >> 5, lane = tid & 31;
    const int wm = wid & 3;          // 4 warp-rows x 16
    const int wn = wid >> 2;         // ST: 2 x 96 cols; PV: 2 x 32 cols
    const int lq = lane >> 2, lr = lane & 3;

    // stage Q tile (tf32-rounded) into Ps region, then load Q fragments to regs
    {
        const float* Qg = g_Q + ((size_t)(b * NH + n) * QLEN + i0) * DH;
        for (int e = tid; e < 64 * 16; e += 256) {
            const int row = e >> 4, c4 = e & 15;
            float4 v = *(const float4*)(Qg + row * DH + c4 * 4);
            float* p = &Ps[row * LPV + c4 * 4];
            p[0] = __uint_as_float(f2tf32(v.x));
            p[1] = __uint_as_float(f2tf32(v.y));
            p[2] = __uint_as_float(f2tf32(v.z));
            p[3] = __uint_as_float(f2tf32(v.w));
        }
        if (tid < 64) Bws[tid] = r_w_bias[n * DH + tid];
    }
    __syncthreads();

    uint32_t af[8][4];
    {
        const int qr = wm * 16 + lq;
#pragma unroll
        for (int kk = 0; kk < 8; kk++) {
            const int k = kk * 8;
            af[kk][0] = __float_as_uint(Ps[qr * LPV + k + lr]);
            af[kk][1] = __float_as_uint(Ps[(qr + 8) * LPV + k + lr]);
            af[kk][2] = __float_as_uint(Ps[qr * LPV + k + 4 + lr]);
            af[kk][3] = __float_as_uint(Ps[(qr + 8) * LPV + k + 4 + lr]);
        }
    }

    float oacc[4][4];
#pragma unroll
    for (int nt = 0; nt < 4; nt++)
#pragma unroll
        for (int u = 0; u < 4; u++) oacc[nt][u] = 0.f;

    // softmax row state (row = tid>>2, replicated over 4 lanes)
    const int srow = tid >> 2;
    const int q4 = tid & 3;
    float mi = NEGINF, li = 0.f;

    const int njt = it + 1;
    for (int jt = 0; jt < njt; jt++) {
        const int j0 = jt * 64;
        const bool diag = (jt == it);
        __syncthreads();   // prev iter's PV reads of Ps/Vt done; KRs/Vt reusable

        // ---- load K rows 0..63, R band rows 64..191, V transposed, r_bias ----
        {
            const float* Kg = g_K + ((size_t)(b * NH + n) * QLEN + j0) * DH;
            const float* Vg = g_V + ((size_t)(b * NH + n) * QLEN + j0) * DH;
            for (int e = tid; e < 64 * 16; e += 256) {
                const int r = e >> 4, c4 = e & 15;
                float4 v = *(const float4*)(Kg + r * DH + c4 * 4);
                float* p = &KRs[r * LKR + c4 * 4];
                p[0] = __uint_as_float(f2tf32(v.x));
                p[1] = __uint_as_float(f2tf32(v.y));
                p[2] = __uint_as_float(f2tf32(v.z));
                p[3] = __uint_as_float(f2tf32(v.w));
            }
            const int m0 = (QLEN - 1) - (i0 + 63) + j0;
            for (int e = tid; e < 128 * 16; e += 256) {
                const int rr = e >> 4, c4 = e & 15;
                const int m = m0 + rr;
                float4 v = make_float4(0.f, 0.f, 0.f, 0.f);
                if (rr < 127 && m < QLEN)
                    v = *(const float4*)(r_emb + ((size_t)m * NH + n) * DH + c4 * 4);
                float* p = &KRs[(64 + rr) * LKR + c4 * 4];
                p[0] = __uint_as_float(f2tf32(v.x));
                p[1] = __uint_as_float(f2tf32(v.y));
                p[2] = __uint_as_float(f2tf32(v.z));
                p[3] = __uint_as_float(f2tf32(v.w));
            }
            for (int e = tid; e < 64 * 16; e += 256) {
                const int j = e & 63, d0 = (e >> 6) * 4;
                float4 v = *(const float4*)(Vg + j * DH + d0);
                Vt[(d0 + 0) * LPV + j] = __uint_as_float(f2tf32(v.x));
                Vt[(d0 + 1) * LPV + j] = __uint_as_float(f2tf32(v.y));
                Vt[(d0 + 2) * LPV + j] = __uint_as_float(f2tf32(v.z));
                Vt[(d0 + 3) * LPV + j] = __uint_as_float(f2tf32(v.w));
            }
            if (tid < 128) {
                const int m = m0 + tid;
                Rbs[tid] = (tid < 127 && m < QLEN) ? r_bias[m * NH + n] : 0.f;
            }
        }
        __syncthreads();

        // Bk[j] = r_w_bias_n . k_j  (warps 0-1; overlaps with mma on other warps)
        if (tid < 64) {
            float s = 0.f;
#pragma unroll
            for (int d = 0; d < 64; d++) s += Bws[d] * KRs[tid * LKR + d];
            Bks[tid] = s;
        }

        // ---- ST = Q . KR^T  (64 x 192) ----
        {
            float sacc[12][4];
#pragma unroll
            for (int nt = 0; nt < 12; nt++)
#pragma unroll
                for (int u = 0; u < 4; u++) sacc[nt][u] = 0.f;
#pragma unroll
            for (int kk = 0; kk < 8; kk++) {
                const int k = kk * 8;
                uint32_t bf[12][2];
#pragma unroll
                for (int nt = 0; nt < 12; nt++) {
                    const int bc = wn * 96 + nt * 8 + lq;
                    bf[nt][0] = __float_as_uint(KRs[bc * LKR + k + lr]);
                    bf[nt][1] = __float_as_uint(KRs[bc * LKR + k + 4 + lr]);
                }
#pragma unroll
                for (int nt = 0; nt < 12; nt++)
                    MMA_TF32(sacc[nt], af[kk], bf[nt]);
            }
            // store fragments to STs
            const int row0 = wm * 16 + lq;
#pragma unroll
            for (int nt = 0; nt < 12; nt++) {
                const int col = wn * 96 + nt * 8 + lr * 2;
                *(float2*)&STs[row0 * LST + col] = make_float2(sacc[nt][0], sacc[nt][1]);
                *(float2*)&STs[(row0 + 8) * LST + col] = make_float2(sacc[nt][2], sacc[nt][3]);
            }
        }
        __syncthreads();

        // ---- softmax (log2 domain, poly exp) ----
        {
            const int toff = 127 - srow;   // T col for jl: toff + jl
            const int roff = 63 - srow;
            float z[16];
            float lmax = NEGINF;
#pragma unroll
            for (int c = 0; c < 16; c++) {
                const int jl = q4 + 4 * c;
                float s = STs[srow * LST + jl] + STs[srow * LST + toff + jl] +
                          Bks[jl] + Rbs[roff + jl];
                s *= SCALE_L2E;
                if (diag && jl > srow) s = NEGINF;
                z[c] = s;
                lmax = fmaxf(lmax, s);
            }
            lmax = fmaxf(lmax, __shfl_xor_sync(0xffffffffu, lmax, 1));
            lmax = fmaxf(lmax, __shfl_xor_sync(0xffffffffu, lmax, 2));
            const float mnew = fmaxf(mi, lmax);
            const float csc = exp2_poly(mi - mnew);
            float lsum = 0.f;
#pragma unroll
            for (int c = 0; c < 16; c++) {
                const float p = exp2_poly(z[c] - mnew);
                Ps[srow * LPV + q4 + 4 * c] = __uint_as_float(f2tf32(p));
                lsum += p;
            }
            lsum += __shfl_xor_sync(0xffffffffu, lsum, 1);
            lsum += __shfl_xor_sync(0xffffffffu, lsum, 2);
            li = li * csc + lsum;
            mi = mnew;
            if (q4 == 0) cscs[srow] = csc;
        }
        __syncthreads();

        // ---- O = O*csc + P.V ----
        {
            const int ar = wm * 16 + lq;
            const float c0 = cscs[ar];
            const float c1 = cscs[ar + 8];
#pragma unroll
            for (int nt = 0; nt < 4; nt++) {
                oacc[nt][0] *= c0; oacc[nt][1] *= c0;
                oacc[nt][2] *= c1; oacc[nt][3] *= c1;
            }
#pragma unroll
            for (int kk = 0; kk < 8; kk++) {
                const int k = kk * 8;
                uint32_t pa[4];
                pa[0] = __float_as_uint(Ps[ar * LPV + k + lr]);
                pa[1] = __float_as_uint(Ps[(ar + 8) * LPV + k + lr]);
                pa[2] = __float_as_uint(Ps[ar * LPV + k + 4 + lr]);
                pa[3] = __float_as_uint(Ps[(ar + 8) * LPV + k + 4 + lr]);
#pragma unroll
                for (int nt = 0; nt < 4; nt++) {
                    uint32_t vb[2];
                    const int bc = wn * 32 + nt * 8 + lq;
                    vb[0] = __float_as_uint(Vt[bc * LPV + k + lr]);
                    vb[1] = __float_as_uint(Vt[bc * LPV + k + 4 + lr]);
                    MMA_TF32(oacc[nt], pa, vb);
                }
            }
        }
    }

    // ---- epilogue ----
    if (q4 == 0) lis[srow] = li;
    __syncthreads();
    {
        const int r0 = wm * 16 + lq;
        const float inv0 = 1.f / lis[r0];
        const float inv1 = 1.f / lis[r0 + 8];
#pragma unroll
        for (int nt = 0; nt < 4; nt++) {
            const int d = wn * 32 + nt * 8 + lr * 2;
            float* p0 = g_att + ((size_t)(i0 + r0) * BSZ + b) * DM + n * DH + d;
            *(float2*)p0 = make_float2(oacc[nt][0] * inv0, oacc[nt][1] * inv0);
            float* p1 = g_att + ((size_t)(i0 + r0 + 8) * BSZ + b) * DM + n * DH + d;
            *(float2*)p1 = make_float2(oacc[nt][2] * inv1, oacc[nt][3] * inv1);
        }
    }
}

// ================= Kernel 4: LayerNorm ========================================
__device__ __forceinline__ float block_sum(float v, float* red) {
#pragma unroll
    for (int o = 16; o > 0; o >>= 1) v += __shfl_xor_sync(0xffffffffu, v, o);
    const int w = threadIdx.x >> 5;
    if ((threadIdx.x & 31) == 0) red[w] = v;
    __syncthreads();
    if (threadIdx.x < 32) {
        float t = (threadIdx.x < 8) ? red[threadIdx.x] : 0.f;
#pragma unroll
        for (int o = 4; o > 0; o >>= 1) t += __shfl_xor_sync(0xffffffffu, t, o);
        if (threadIdx.x == 0) red[0] = t;
    }
    __syncthreads();
    const float r = red[0];
    __syncthreads();
    return r;
}

__global__ void __launch_bounds__(256) ln_kernel(const float* __restrict__ gamma,
                                                 const float* __restrict__ beta,
                                                 float* __restrict__ out) {
    __shared__ float red[8];
    const int r = blockIdx.x;
    const float* x = g_res + (size_t)r * DM;
    const int tid = threadIdx.x;
    float v[3];
#pragma unroll
    for (int u = 0; u < 3; u++) v[u] = x[tid + u * 256];
    const float total = block_sum(v[0] + v[1] + v[2], red);
    const float mu = total * (1.f / DM);
    float sq = 0.f;
#pragma unroll
    for (int u = 0; u < 3; u++) { const float d = v[u] - mu; sq += d * d; }
    const float var = block_sum(sq, red) * (1.f / DM);
    const float inv = rsqrtf(var + 1e-5f);
#pragma unroll
    for (int u = 0; u < 3; u++) {
        const int c = tid + u * 256;
        out[(size_t)r * DM + c] = (v[u] - mu) * inv * gamma[c] + beta[c];
    }
}

// ================= launch =====================================================
extern "C" void kernel_launch(void* const* d_in, const int* in_sizes, int n_in,
                              void* d_out, int out_size) {
    const float* w        = (const float*)d_in[0];
    const float* r_emb    = (const float*)d_in[1];
    const float* r_w_bias = (const float*)d_in[2];
    const float* r_bias   = (const float*)d_in[3];
    const float* qkv_w    = (const float*)d_in[4];
    const float* o_w      = (const float*)d_in[5];
    const float* ln_g     = (const float*)d_in[6];
    const float* ln_b     = (const float*)d_in[7];
    float* out = (float*)d_out;

    float* g_att_ptr = nullptr;
    cudaGetSymbolAddress((void**)&g_att_ptr, g_att);

    // QKV projection
    mma_gemm_kernel<0><<<dim3(QLEN * BSZ / BM, 3 * DM / BN), 256>>>(w, qkv_w, nullptr, DM);

    // fused tensor-core rel-attention
    const int attn_smem = ATTN_SMEM_FLOATS * (int)sizeof(float);   // ~135.5 KB
    (void)cudaFuncSetAttribute(attn_kernel, cudaFuncAttributeMaxDynamicSharedMemorySize, attn_smem);
    attn_kernel<<<dim3(QLEN / 64, BSZ * NH), 256, attn_smem>>>(r_emb, r_w_bias, r_bias);

    // O-projection + residual
    mma_gemm_kernel<1><<<dim3(QLEN * BSZ / BM, DM / BN), 256>>>(g_att_ptr, o_w, w, DM);

    ln_kernel<<<QLEN * BSZ, 256>>>(ln_g, ln_b, out);
}

// round 7
// speedup vs baseline: 3.3619x; 1.5656x over previous
#include <cuda_runtime.h>
#include <cstdint>

#define QLEN 2048
#define BSZ 2
#define NH 12
#define DH 64
#define DM 768
#define NEGINF (-1e30f)
#define ATTN_SCALE 0.125f                 // 1/sqrt(64)
#define SCALE_L2E 0.1803368801111244f     // ATTN_SCALE * log2(e)

// ---------------- scratch (static device allocations; no cudaMalloc allowed) ----
__device__ float g_Q[BSZ * NH * QLEN * DH];     // [b][n][i][d]
__device__ float g_K[BSZ * NH * QLEN * DH];
__device__ float g_V[BSZ * NH * QLEN * DH];
__device__ float g_att[QLEN * BSZ * DM];        // attn_vec, row r = i*BSZ+b
__device__ float g_res[QLEN * BSZ * DM];        // w + attn_out

__device__ __forceinline__ uint32_t f2tf32(float x) {
    uint32_t u;
    asm("cvt.rna.tf32.f32 %0, %1;" : "=r"(u) : "f"(x));
    return u;
}
__device__ __forceinline__ uint32_t smem_u32(const void* p) {
    uint32_t a;
    asm("{ .reg .u64 t; cvta.to.shared.u64 t, %1; cvt.u32.u64 %0, t; }" : "=r"(a) : "l"(p));
    return a;
}
__device__ __forceinline__ void cp16(uint32_t dst, const void* src, uint32_t srcsize) {
    asm volatile("cp.async.cg.shared.global [%0], [%1], 16, %2;"
                 :: "r"(dst), "l"(src), "r"(srcsize) : "memory");
}
#define CP_COMMIT() asm volatile("cp.async.commit_group;" ::: "memory")
#define CP_WAIT0()  asm volatile("cp.async.wait_group 0;" ::: "memory")

#define MMA_TF32(d, a, b)                                                          \
    asm volatile("mma.sync.aligned.m16n8k8.row.col.f32.tf32.tf32.f32 "             \
                 "{%0,%1,%2,%3}, {%4,%5,%6,%7}, {%8,%9}, {%0,%1,%2,%3};"           \
                 : "+f"((d)[0]), "+f"((d)[1]), "+f"((d)[2]), "+f"((d)[3])          \
                 : "r"((a)[0]), "r"((a)[1]), "r"((a)[2]), "r"((a)[3]),             \
                   "r"((b)[0]), "r"((b)[1]))

// fast 2^t for t <= 0 (clamped); deg-4 Taylor in f*ln2; rel err <= ~9e-5
__device__ __forceinline__ float exp2_poly(float t) {
    t = fmaxf(t, -100.f);
    const float r = rintf(t);
    const float y = (t - r) * 0.6931471805599453f;
    float p = 0.041666667f;
    p = p * y + 0.166666667f;
    p = p * y + 0.5f;
    p = p * y + 1.0f;
    p = p * y + 1.0f;
    const int ri = (int)r;
    return p * __int_as_float((ri + 127) << 23);
}

// ================= mma.sync tf32 projection GEMM (unchanged, works) ============
#define BM 128
#define BN 128
#define BKC 32
#define LDP (BKC + 4)

template <int MODE>
__global__ void __launch_bounds__(256) mma_gemm_kernel(const float* __restrict__ A,
                                                       const float* __restrict__ B,
                                                       const float* __restrict__ W,
                                                       int kdim) {
    __shared__ float As[BM][LDP];
    __shared__ float Bs[BN][LDP];

    const int tid = threadIdx.x;
    const int wid = tid >> 5, lane = tid & 31;
    const int wm = wid & 3;
    const int wn = wid >> 2;
    const int rb = blockIdx.x * BM;
    const int cb = blockIdx.y * BN;
    const int lq = lane >> 2;
    const int lr = lane & 3;

    float acc[2][8][4];
#pragma unroll
    for (int mt = 0; mt < 2; mt++)
#pragma unroll
        for (int nt = 0; nt < 8; nt++)
#pragma unroll
            for (int u = 0; u < 4; u++) acc[mt][nt][u] = 0.f;

    const int nchunk = kdim / BKC;
    for (int c = 0; c < nchunk; c++) {
        const int k0 = c * BKC;
#pragma unroll
        for (int e2 = 0; e2 < 4; e2++) {
            const int e = tid + e2 * 256;
            const int row = e >> 3, c4 = e & 7;
            float4 av = *(const float4*)(A + (size_t)(rb + row) * kdim + k0 + c4 * 4);
            float* pa = &As[row][c4 * 4];
            pa[0] = __uint_as_float(f2tf32(av.x));
            pa[1] = __uint_as_float(f2tf32(av.y));
            pa[2] = __uint_as_float(f2tf32(av.z));
            pa[3] = __uint_as_float(f2tf32(av.w));
            float4 bv = *(const float4*)(B + (size_t)(cb + row) * kdim + k0 + c4 * 4);
            float* pb = &Bs[row][c4 * 4];
            pb[0] = __uint_as_float(f2tf32(bv.x));
            pb[1] = __uint_as_float(f2tf32(bv.y));
            pb[2] = __uint_as_float(f2tf32(bv.z));
            pb[3] = __uint_as_float(f2tf32(bv.w));
        }
        __syncthreads();
#pragma unroll
        for (int kk = 0; kk < BKC / 8; kk++) {
            const int k = kk * 8;
            uint32_t af[2][4];
#pragma unroll
            for (int mt = 0; mt < 2; mt++) {
                const int ar = wm * 32 + mt * 16 + lq;
                af[mt][0] = __float_as_uint(As[ar][k + lr]);
                af[mt][1] = __float_as_uint(As[ar + 8][k + lr]);
                af[mt][2] = __float_as_uint(As[ar][k + 4 + lr]);
                af[mt][3] = __float_as_uint(As[ar + 8][k + 4 + lr]);
            }
            uint32_t bf[8][2];
#pragma unroll
            for (int nt = 0; nt < 8; nt++) {
                const int bc = wn * 64 + nt * 8 + lq;
                bf[nt][0] = __float_as_uint(Bs[bc][k + lr]);
                bf[nt][1] = __float_as_uint(Bs[bc][k + 4 + lr]);
            }
#pragma unroll
            for (int mt = 0; mt < 2; mt++)
#pragma unroll
                for (int nt = 0; nt < 8; nt++)
                    MMA_TF32(acc[mt][nt], af[mt], bf[nt]);
        }
        __syncthreads();
    }

#pragma unroll
    for (int mt = 0; mt < 2; mt++) {
#pragma unroll
        for (int half = 0; half < 2; half++) {
            const int r = rb + wm * 32 + mt * 16 + lq + half * 8;
#pragma unroll
            for (int nt = 0; nt < 8; nt++) {
                const int h = cb + wn * 64 + nt * 8 + lr * 2;
                const float v0 = acc[mt][nt][half * 2 + 0];
                const float v1 = acc[mt][nt][half * 2 + 1];
                if (MODE == 0) {
                    const int i = r >> 1, b = r & 1;
                    const int sel = h / DM;
                    const int rem = h - sel * DM;
                    const int n = rem >> 6, d0 = rem & 63;
                    float* dst = (sel == 0) ? g_Q : (sel == 1) ? g_K : g_V;
                    float2* p = (float2*)(dst + ((size_t)(b * NH + n) * QLEN + i) * DH + d0);
                    *p = make_float2(v0, v1);
                } else {
                    const float2 wv = *(const float2*)(W + (size_t)r * DM + h);
                    *(float2*)(g_res + (size_t)r * DM + h) =
                        make_float2(v0 + wv.x, v1 + wv.y);
                }
            }
        }
    }
}

// ================= Kernel 2: cp.async-pipelined tensor-core rel-attention ======
#define LKR 68
#define LV 72
#define LST 196
#define LPQ 68
// stage layout (floats): KR[192][68] | V[64][72] | Rb[128]
#define ST_KR 0
#define ST_V  (192 * LKR)                   // 13056
#define ST_RB (ST_V + 64 * LV)              // 17664
#define STAGE_FLOATS (ST_RB + 128)          // 17792
// full smem (floats)
#define OF_ST2  (2 * STAGE_FLOATS)          // 35584
#define OF_PQ   (OF_ST2 + 64 * LST)         // 48128 (Q staging, then P)
#define OF_BW   (OF_PQ + 64 * LPQ)          // 52480
#define OF_BK   (OF_BW + 64)
#define OF_CSC  (OF_BK + 64)
#define OF_LI   (OF_CSC + 64)
#define ATTN_SMEM_FLOATS (OF_LI + 64)       // 52736 floats = 210944 B

__global__ void __launch_bounds__(256, 1) attn_kernel(const float* __restrict__ r_emb,
                                                      const float* __restrict__ r_bias,
                                                      const float* __restrict__ r_w_bias) {
    extern __shared__ float sm[];
    const uint32_t smb = smem_u32(sm);
    float* STs = sm + OF_ST2;
    float* Ps  = sm + OF_PQ;
    float* Bws = sm + OF_BW;
    float* Bks = sm + OF_BK;
    float* cscs = sm + OF_CSC;
    float* lis  = sm + OF_LI;

    const int bn = blockIdx.y;
    const int b = bn / NH, n = bn % NH;
    const int it = (gridDim.x - 1) - blockIdx.x;   // longest blocks first
    const int i0 = it * 64;
    const int tid = threadIdx.x;
    const int wid = tid >> 5, lane = tid & 31;
    const int wm = wid & 3;
    const int wn = wid >> 2;
    const int lq = lane >> 2, lr = lane & 3;

    const float* Kg0 = g_K + ((size_t)(b * NH + n) * QLEN) * DH;
    const float* Vg0 = g_V + ((size_t)(b * NH + n) * QLEN) * DH;

    // ---- prologue: Q tile (plain loads, raw fp32), r_w_bias ----
    {
        const float* Qg = g_Q + ((size_t)(b * NH + n) * QLEN + i0) * DH;
#pragma unroll
        for (int e2 = 0; e2 < 4; e2++) {
            const int e = tid + e2 * 256;
            const int row = e >> 4, c4 = e & 15;
            *(float4*)&Ps[row * LPQ + c4 * 4] = *(const float4*)(Qg + row * DH + c4 * 4);
        }
        if (tid < 64) Bws[tid] = r_w_bias[n * DH + tid];
    }

    // ---- prologue: issue cp.async for stage 0 (jt = 0) ----
    {
        const int m0 = 1984 - i0;   // j0 = 0
#pragma unroll
        for (int e2 = 0; e2 < 16; e2++) {
            const int e = tid + e2 * 256;
            const int row = e >> 4, c4 = e & 15;
            if (row < 64) {
                cp16(smb + (ST_KR + row * LKR) * 4 + c4 * 16, Kg0 + row * DH + c4 * 4, 16);
            } else if (row < 192) {
                const int rr = row - 64;
                const int m = m0 + rr;
                const uint32_t ok = (rr < 127 && m < QLEN) ? 16u : 0u;
                const float* src = r_emb + ((size_t)(ok ? m : 0) * NH + n) * DH + c4 * 4;
                cp16(smb + (ST_KR + row * LKR) * 4 + c4 * 16, src, ok);
            } else {
                const int j = row - 192;
                cp16(smb + (ST_V + j * LV) * 4 + c4 * 16, Vg0 + j * DH + c4 * 4, 16);
            }
        }
        CP_COMMIT();
        if (tid < 128) {
            const int m = m0 + tid;
            sm[ST_RB + tid] = (tid < 127 && m < QLEN) ? r_bias[m * NH + n] : 0.f;
        }
    }
    __syncthreads();

    // Q fragments -> registers (Ps region is reused for P afterwards)
    uint32_t af[8][4];
    {
        const int qr = wm * 16 + lq;
#pragma unroll
        for (int kk = 0; kk < 8; kk++) {
            const int k = kk * 8;
            af[kk][0] = __float_as_uint(Ps[qr * LPQ + k + lr]);
            af[kk][1] = __float_as_uint(Ps[(qr + 8) * LPQ + k + lr]);
            af[kk][2] = __float_as_uint(Ps[qr * LPQ + k + 4 + lr]);
            af[kk][3] = __float_as_uint(Ps[(qr + 8) * LPQ + k + 4 + lr]);
        }
    }

    float oacc[4][4];
#pragma unroll
    for (int nt = 0; nt < 4; nt++)
#pragma unroll
        for (int u = 0; u < 4; u++) oacc[nt][u] = 0.f;

    const int srow = tid >> 2;
    const int q4 = tid & 3;
    float mi = NEGINF, li = 0.f;

    const int njt = it + 1;
    for (int jt = 0; jt < njt; jt++) {
        const bool diag = (jt == it);
        const float* KRcur = sm + (jt & 1) * STAGE_FLOATS;
        const float* Vcur  = KRcur + ST_V;
        const float* Rbcur = KRcur + ST_RB;

        CP_WAIT0();
        __syncthreads();   // stage jt resident; all warps past previous iter's reads

        // ---- issue prefetch for stage jt+1 into the other buffer ----
        if (jt + 1 < njt) {
            const int j0n = (jt + 1) * 64;
            const int m0n = 1984 - i0 + j0n;
            const uint32_t nb = smb + ((jt + 1) & 1) * STAGE_FLOATS * 4;
            const float* Kgn = Kg0 + (size_t)j0n * DH;
            const float* Vgn = Vg0 + (size_t)j0n * DH;
#pragma unroll
            for (int e2 = 0; e2 < 16; e2++) {
                const int e = tid + e2 * 256;
                const int row = e >> 4, c4 = e & 15;
                if (row < 64) {
                    cp16(nb + (ST_KR + row * LKR) * 4 + c4 * 16, Kgn + row * DH + c4 * 4, 16);
                } else if (row < 192) {
                    const int rr = row - 64;
                    const int m = m0n + rr;
                    const uint32_t ok = (rr < 127 && m < QLEN) ? 16u : 0u;
                    const float* src = r_emb + ((size_t)(ok ? m : 0) * NH + n) * DH + c4 * 4;
                    cp16(nb + (ST_KR + row * LKR) * 4 + c4 * 16, src, ok);
                } else {
                    const int j = row - 192;
                    cp16(nb + (ST_V + j * LV) * 4 + c4 * 16, Vgn + j * DH + c4 * 4, 16);
                }
            }
            CP_COMMIT();
            if (tid < 128) {
                const int m = m0n + tid;
                float* rbn = sm + ((jt + 1) & 1) * STAGE_FLOATS + ST_RB;
                rbn[tid] = (tid < 127 && m < QLEN) ? r_bias[m * NH + n] : 0.f;
            }
        }

        // Bk[j] = r_w_bias_n . k_j  (warps 0-1, overlaps ST mma of warps 2-7)
        if (tid < 64) {
            float s = 0.f;
#pragma unroll
            for (int d = 0; d < 64; d++) s += Bws[d] * KRcur[tid * LKR + d];
            Bks[tid] = s;
        }

        // ---- ST = Q . KR^T  (64 x 192) ----
        {
            float sacc[12][4];
#pragma unroll
            for (int nt = 0; nt < 12; nt++)
#pragma unroll
                for (int u = 0; u < 4; u++) sacc[nt][u] = 0.f;
#pragma unroll
            for (int kk = 0; kk < 8; kk++) {
                const int k = kk * 8;
                uint32_t bf[12][2];
#pragma unroll
                for (int nt = 0; nt < 12; nt++) {
                    const int bc = wn * 96 + nt * 8 + lq;
                    bf[nt][0] = __float_as_uint(KRcur[bc * LKR + k + lr]);
                    bf[nt][1] = __float_as_uint(KRcur[bc * LKR + k + 4 + lr]);
                }
#pragma unroll
                for (int nt = 0; nt < 12; nt++)
                    MMA_TF32(sacc[nt], af[kk], bf[nt]);
            }
            const int row0 = wm * 16 + lq;
#pragma unroll
            for (int nt = 0; nt < 12; nt++) {
                const int col = wn * 96 + nt * 8 + lr * 2;
                *(float2*)&STs[row0 * LST + col] = make_float2(sacc[nt][0], sacc[nt][1]);
                *(float2*)&STs[(row0 + 8) * LST + col] = make_float2(sacc[nt][2], sacc[nt][3]);
            }
        }
        __syncthreads();

        // ---- softmax (log2 domain, poly exp) ----
        {
            const int toff = 127 - srow;
            const int roff = 63 - srow;
            float z[16];
            float lmax = NEGINF;
#pragma unroll
            for (int c = 0; c < 16; c++) {
                const int jl = q4 + 4 * c;
                float s = STs[srow * LST + jl] + STs[srow * LST + toff + jl] +
                          Bks[jl] + Rbcur[roff + jl];
                s *= SCALE_L2E;
                if (diag && jl > srow) s = NEGINF;
                z[c] = s;
                lmax = fmaxf(lmax, s);
            }
            lmax = fmaxf(lmax, __shfl_xor_sync(0xffffffffu, lmax, 1));
            lmax = fmaxf(lmax, __shfl_xor_sync(0xffffffffu, lmax, 2));
            const float mnew = fmaxf(mi, lmax);
            const float csc = exp2_poly(mi - mnew);
            float lsum = 0.f;
#pragma unroll
            for (int c = 0; c < 16; c++) {
                const float p = exp2_poly(z[c] - mnew);
                Ps[srow * LPQ + q4 + 4 * c] = p;
                lsum += p;
            }
            lsum += __shfl_xor_sync(0xffffffffu, lsum, 1);
            lsum += __shfl_xor_sync(0xffffffffu, lsum, 2);
            li = li * csc + lsum;
            mi = mnew;
            if (q4 == 0) cscs[srow] = csc;
        }
        __syncthreads();

        // ---- O = O*csc + P.V   (V row-major [j][d], stride 72) ----
        {
            const int ar = wm * 16 + lq;
            const float c0 = cscs[ar];
            const float c1 = cscs[ar + 8];
#pragma unroll
            for (int nt = 0; nt < 4; nt++) {
                oacc[nt][0] *= c0; oacc[nt][1] *= c0;
                oacc[nt][2] *= c1; oacc[nt][3] *= c1;
            }
#pragma unroll
            for (int kk = 0; kk < 8; kk++) {
                const int k = kk * 8;
                uint32_t pa[4];
                pa[0] = __float_as_uint(Ps[ar * LPQ + k + lr]);
                pa[1] = __float_as_uint(Ps[(ar + 8) * LPQ + k + lr]);
                pa[2] = __float_as_uint(Ps[ar * LPQ + k + 4 + lr]);
                pa[3] = __float_as_uint(Ps[(ar + 8) * LPQ + k + 4 + lr]);
#pragma unroll
                for (int nt = 0; nt < 4; nt++) {
                    const int d = wn * 32 + nt * 8 + lq;
                    uint32_t vb[2];
                    vb[0] = __float_as_uint(Vcur[(k + lr) * LV + d]);
                    vb[1] = __float_as_uint(Vcur[(k + 4 + lr) * LV + d]);
                    MMA_TF32(oacc[nt], pa, vb);
                }
            }
        }
    }

    // ---- epilogue ----
    if (q4 == 0) lis[srow] = li;
    __syncthreads();
    {
        const int r0 = wm * 16 + lq;
        const float inv0 = 1.f / lis[r0];
        const float inv1 = 1.f / lis[r0 + 8];
#pragma unroll
        for (int nt = 0; nt < 4; nt++) {
            const int d = wn * 32 + nt * 8 + lr * 2;
            float* p0 = g_att + ((size_t)(i0 + r0) * BSZ + b) * DM + n * DH + d;
            *(float2*)p0 = make_float2(oacc[nt][0] * inv0, oacc[nt][1] * inv0);
            float* p1 = g_att + ((size_t)(i0 + r0 + 8) * BSZ + b) * DM + n * DH + d;
            *(float2*)p1 = make_float2(oacc[nt][2] * inv1, oacc[nt][3] * inv1);
        }
    }
}

// ================= Kernel 4: LayerNorm ========================================
__device__ __forceinline__ float block_sum(float v, float* red) {
#pragma unroll
    for (int o = 16; o > 0; o >>= 1) v += __shfl_xor_sync(0xffffffffu, v, o);
    const int w = threadIdx.x >> 5;
    if ((threadIdx.x & 31) == 0) red[w] = v;
    __syncthreads();
    if (threadIdx.x < 32) {
        float t = (threadIdx.x < 8) ? red[threadIdx.x] : 0.f;
#pragma unroll
        for (int o = 4; o > 0; o >>= 1) t += __shfl_xor_sync(0xffffffffu, t, o);
        if (threadIdx.x == 0) red[0] = t;
    }
    __syncthreads();
    const float r = red[0];
    __syncthreads();
    return r;
}

__global__ void __launch_bounds__(256) ln_kernel(const float* __restrict__ gamma,
                                                 const float* __restrict__ beta,
                                                 float* __restrict__ out) {
    __shared__ float red[8];
    const int r = blockIdx.x;
    const float* x = g_res + (size_t)r * DM;
    const int tid = threadIdx.x;
    float v[3];
#pragma unroll
    for (int u = 0; u < 3; u++) v[u] = x[tid + u * 256];
    const float total = block_sum(v[0] + v[1] + v[2], red);
    const float mu = total * (1.f / DM);
    float sq = 0.f;
#pragma unroll
    for (int u = 0; u < 3; u++) { const float d = v[u] - mu; sq += d * d; }
    const float var = block_sum(sq, red) * (1.f / DM);
    const float inv = rsqrtf(var + 1e-5f);
#pragma unroll
    for (int u = 0; u < 3; u++) {
        const int c = tid + u * 256;
        out[(size_t)r * DM + c] = (v[u] - mu) * inv * gamma[c] + beta[c];
    }
}

// ================= launch =====================================================
extern "C" void kernel_launch(void* const* d_in, const int* in_sizes, int n_in,
                              void* d_out, int out_size) {
    const float* w        = (const float*)d_in[0];
    const float* r_emb    = (const float*)d_in[1];
    const float* r_w_bias = (const float*)d_in[2];
    const float* r_bias   = (const float*)d_in[3];
    const float* qkv_w    = (const float*)d_in[4];
    const float* o_w      = (const float*)d_in[5];
    const float* ln_g     = (const float*)d_in[6];
    const float* ln_b     = (const float*)d_in[7];
    float* out = (float*)d_out;

    float* g_att_ptr = nullptr;
    cudaGetSymbolAddress((void**)&g_att_ptr, g_att);

    // QKV projection
    mma_gemm_kernel<0><<<dim3(QLEN * BSZ / BM, 3 * DM / BN), 256>>>(w, qkv_w, nullptr, DM);

    // pipelined tensor-core rel-attention
    const int attn_smem = ATTN_SMEM_FLOATS * (int)sizeof(float);   // ~206 KB
    (void)cudaFuncSetAttribute(attn_kernel, cudaFuncAttributeMaxDynamicSharedMemorySize, attn_smem);
    attn_kernel<<<dim3(QLEN / 64, BSZ * NH), 256, attn_smem>>>(r_emb, r_bias, r_w_bias);

    // O-projection + residual
    mma_gemm_kernel<1><<<dim3(QLEN * BSZ / BM, DM / BN), 256>>>(g_att_ptr, o_w, w, DM);

    ln_kernel<<<QLEN * BSZ, 256>>>(ln_g, ln_b, out);
}

// round 8
// speedup vs baseline: 4.0618x; 1.2082x over previous
#include <cuda_runtime.h>
#include <cuda_bf16.h>
#include <cstdint>

#define QLEN 2048
#define BSZ 2
#define NH 12
#define DH 64
#define DM 768
#define NEGINF (-1e30f)
#define SCALE_L2E 0.1803368801111244f     // (1/sqrt(64)) * log2(e)

// ---------------- scratch (static device allocations) --------------------------
__device__ __nv_bfloat16 g_Qh[BSZ * NH * QLEN * DH];   // [b][n][i][d], pre-scaled by SCALE_L2E
__device__ __nv_bfloat16 g_Kh[BSZ * NH * QLEN * DH];   // [b][n][j][d]
__device__ __nv_bfloat16 g_Vt[BSZ * NH * DH * QLEN];   // [b][n][d][j]  (transposed)
__device__ __nv_bfloat16 g_Rh[NH * QLEN * DH];         // [n][m][d]
__device__ float g_att[QLEN * BSZ * DM];               // attn_vec, row r = i*BSZ+b
__device__ float g_res[QLEN * BSZ * DM];               // w + attn_out

__device__ __forceinline__ uint32_t f2tf32(float x) {
    uint32_t u;
    asm("cvt.rna.tf32.f32 %0, %1;" : "=r"(u) : "f"(x));
    return u;
}
__device__ __forceinline__ uint32_t smem_u32(const void* p) {
    uint32_t a;
    asm("{ .reg .u64 t; cvta.to.shared.u64 t, %1; cvt.u32.u64 %0, t; }" : "=r"(a) : "l"(p));
    return a;
}
__device__ __forceinline__ void cp16(uint32_t dst, const void* src, uint32_t srcsize) {
    asm volatile("cp.async.cg.shared.global [%0], [%1], 16, %2;"
                 :: "r"(dst), "l"(src), "r"(srcsize) : "memory");
}
#define CP_COMMIT() asm volatile("cp.async.commit_group;" ::: "memory")
#define CP_WAIT0()  asm volatile("cp.async.wait_group 0;" ::: "memory")

#define MMA_TF32(d, a, b)                                                          \
    asm volatile("mma.sync.aligned.m16n8k8.row.col.f32.tf32.tf32.f32 "             \
                 "{%0,%1,%2,%3}, {%4,%5,%6,%7}, {%8,%9}, {%0,%1,%2,%3};"           \
                 : "+f"((d)[0]), "+f"((d)[1]), "+f"((d)[2]), "+f"((d)[3])          \
                 : "r"((a)[0]), "r"((a)[1]), "r"((a)[2]), "r"((a)[3]),             \
                   "r"((b)[0]), "r"((b)[1]))

#define MMA_BF16(d, a, b)                                                          \
    asm volatile("mma.sync.aligned.m16n8k16.row.col.f32.bf16.bf16.f32 "            \
                 "{%0,%1,%2,%3}, {%4,%5,%6,%7}, {%8,%9}, {%0,%1,%2,%3};"           \
                 : "+f"((d)[0]), "+f"((d)[1]), "+f"((d)[2]), "+f"((d)[3])          \
                 : "r"((a)[0]), "r"((a)[1]), "r"((a)[2]), "r"((a)[3]),             \
                   "r"((b)[0]), "r"((b)[1]))

// fast 2^t for t <= 0 (clamped); deg-4 Taylor in f*ln2; rel err <= ~9e-5
__device__ __forceinline__ float exp2_poly(float t) {
    t = fmaxf(t, -100.f);
    const float r = rintf(t);
    const float y = (t - r) * 0.6931471805599453f;
    float p = 0.041666667f;
    p = p * y + 0.166666667f;
    p = p * y + 0.5f;
    p = p * y + 1.0f;
    p = p * y + 1.0f;
    const int ri = (int)r;
    return p * __int_as_float((ri + 127) << 23);
}

// ================= mma.sync tf32 projection GEMM ===============================
// MODE 0: scatter bf16 into g_Qh (pre-scaled) / g_Kh / g_Vt.  MODE 1: +W -> g_res.
#define BM 128
#define BN 128
#define BKC 32
#define LDP (BKC + 4)

template <int MODE>
__global__ void __launch_bounds__(256) mma_gemm_kernel(const float* __restrict__ A,
                                                       const float* __restrict__ B,
                                                       const float* __restrict__ W,
                                                       int kdim) {
    __shared__ float As[BM][LDP];
    __shared__ float Bs[BN][LDP];

    const int tid = threadIdx.x;
    const int wid = tid >> 5, lane = tid & 31;
    const int wm = wid & 3;
    const int wn = wid >> 2;
    const int rb = blockIdx.x * BM;
    const int cb = blockIdx.y * BN;
    const int lq = lane >> 2;
    const int lr = lane & 3;

    float acc[2][8][4];
#pragma unroll
    for (int mt = 0; mt < 2; mt++)
#pragma unroll
        for (int nt = 0; nt < 8; nt++)
#pragma unroll
            for (int u = 0; u < 4; u++) acc[mt][nt][u] = 0.f;

    const int nchunk = kdim / BKC;
    for (int c = 0; c < nchunk; c++) {
        const int k0 = c * BKC;
#pragma unroll
        for (int e2 = 0; e2 < 4; e2++) {
            const int e = tid + e2 * 256;
            const int row = e >> 3, c4 = e & 7;
            float4 av = *(const float4*)(A + (size_t)(rb + row) * kdim + k0 + c4 * 4);
            float* pa = &As[row][c4 * 4];
            pa[0] = __uint_as_float(f2tf32(av.x));
            pa[1] = __uint_as_float(f2tf32(av.y));
            pa[2] = __uint_as_float(f2tf32(av.z));
            pa[3] = __uint_as_float(f2tf32(av.w));
            float4 bv = *(const float4*)(B + (size_t)(cb + row) * kdim + k0 + c4 * 4);
            float* pb = &Bs[row][c4 * 4];
            pb[0] = __uint_as_float(f2tf32(bv.x));
            pb[1] = __uint_as_float(f2tf32(bv.y));
            pb[2] = __uint_as_float(f2tf32(bv.z));
            pb[3] = __uint_as_float(f2tf32(bv.w));
        }
        __syncthreads();
#pragma unroll
        for (int kk = 0; kk < BKC / 8; kk++) {
            const int k = kk * 8;
            uint32_t af[2][4];
#pragma unroll
            for (int mt = 0; mt < 2; mt++) {
                const int ar = wm * 32 + mt * 16 + lq;
                af[mt][0] = __float_as_uint(As[ar][k + lr]);
                af[mt][1] = __float_as_uint(As[ar + 8][k + lr]);
                af[mt][2] = __float_as_uint(As[ar][k + 4 + lr]);
                af[mt][3] = __float_as_uint(As[ar + 8][k + 4 + lr]);
            }
            uint32_t bf[8][2];
#pragma unroll
            for (int nt = 0; nt < 8; nt++) {
                const int bc = wn * 64 + nt * 8 + lq;
                bf[nt][0] = __float_as_uint(Bs[bc][k + lr]);
                bf[nt][1] = __float_as_uint(Bs[bc][k + 4 + lr]);
            }
#pragma unroll
            for (int mt = 0; mt < 2; mt++)
#pragma unroll
                for (int nt = 0; nt < 8; nt++)
                    MMA_TF32(acc[mt][nt], af[mt], bf[nt]);
        }
        __syncthreads();
    }

#pragma unroll
    for (int mt = 0; mt < 2; mt++) {
#pragma unroll
        for (int half = 0; half < 2; half++) {
            const int r = rb + wm * 32 + mt * 16 + lq + half * 8;
#pragma unroll
            for (int nt = 0; nt < 8; nt++) {
                const int h = cb + wn * 64 + nt * 8 + lr * 2;
                const float v0 = acc[mt][nt][half * 2 + 0];
                const float v1 = acc[mt][nt][half * 2 + 1];
                if (MODE == 0) {
                    const int i = r >> 1, b = r & 1;
                    const int sel = h / DM;
                    const int rem = h - sel * DM;
                    const int n = rem >> 6, d0 = rem & 63;
                    if (sel == 0) {
                        __nv_bfloat162 p = __floats2bfloat162_rn(v0 * SCALE_L2E, v1 * SCALE_L2E);
                        *(__nv_bfloat162*)(g_Qh + ((size_t)(b * NH + n) * QLEN + i) * DH + d0) = p;
                    } else if (sel == 1) {
                        __nv_bfloat162 p = __floats2bfloat162_rn(v0, v1);
                        *(__nv_bfloat162*)(g_Kh + ((size_t)(b * NH + n) * QLEN + i) * DH + d0) = p;
                    } else {
                        g_Vt[((size_t)(b * NH + n) * DH + d0) * QLEN + i] = __float2bfloat16(v0);
                        g_Vt[((size_t)(b * NH + n) * DH + d0 + 1) * QLEN + i] = __float2bfloat16(v1);
                    }
                } else {
                    const float2 wv = *(const float2*)(W + (size_t)r * DM + h);
                    *(float2*)(g_res + (size_t)r * DM + h) =
                        make_float2(v0 + wv.x, v1 + wv.y);
                }
            }
        }
    }
}

// ================= r_emb -> bf16 head-major ===================================
__global__ void __launch_bounds__(256) conv_r_kernel(const float* __restrict__ r_emb) {
    const int m = blockIdx.x;
    const int tid = threadIdx.x;
#pragma unroll
    for (int u = 0; u < 3; u++) {
        const int e = tid + u * 256;            // 0..767
        const int n = e >> 6, d = e & 63;
        g_Rh[((size_t)n * QLEN + m) * DH + d] =
            __float2bfloat16(r_emb[(size_t)m * NH * DH + e]);
    }
}

// ================= Kernel 2: bf16 cp.async-pipelined flash rel-attention =======
#define LH 72                                 // bf16 row stride (144 B)
#define LST 196                               // fp32 score row stride
// stage layout (bytes): KR[192][72 bf16] | Vt[64][72 bf16] | Rb[128 f32]
#define SG_KR 0
#define SG_V  (192 * LH * 2)                  // 27648
#define SG_RB (SG_V + 64 * LH * 2)            // 36864
#define STAGE_BYTES (SG_RB + 128 * 4)         // 37376
// full smem (bytes)
#define OF_ST  (2 * STAGE_BYTES)              // 74752 : STs fp32 64x196
#define OF_PQ  (OF_ST + 64 * LST * 4)         // 124928 : P/Q bf16 64x72
#define OF_BW  (OF_PQ + 64 * LH * 2)          // 134144
#define OF_BK  (OF_BW + 256)
#define OF_CSC (OF_BK + 256)
#define OF_LI  (OF_CSC + 256)
#define ATTN_SMEM_BYTES (OF_LI + 256)         // 135168

__global__ void __launch_bounds__(256, 1) attn_kernel(const float* __restrict__ r_bias,
                                                      const float* __restrict__ r_w_bias) {
    extern __shared__ char sm[];
    const uint32_t smb = smem_u32(sm);
    float* STs = (float*)(sm + OF_ST);
    __nv_bfloat16* Ph = (__nv_bfloat16*)(sm + OF_PQ);
    float* Bws = (float*)(sm + OF_BW);
    float* Bks = (float*)(sm + OF_BK);
    float* cscs = (float*)(sm + OF_CSC);
    float* lis  = (float*)(sm + OF_LI);

    const int bn = blockIdx.y;
    const int b = bn / NH, n = bn % NH;
    const int it = (gridDim.x - 1) - blockIdx.x;   // longest blocks first
    const int i0 = it * 64;
    const int tid = threadIdx.x;
    const int wid = tid >> 5, lane = tid & 31;
    const int wm = wid & 3;
    const int wn = wid >> 2;
    const int lq = lane >> 2, lr = lane & 3;

    const __nv_bfloat16* Kg0 = g_Kh + (size_t)(b * NH + n) * QLEN * DH;
    const __nv_bfloat16* Vt0 = g_Vt + (size_t)(b * NH + n) * DH * QLEN;
    const __nv_bfloat16* Rg0 = g_Rh + (size_t)n * QLEN * DH;

    // ---- prologue: Q tile (bf16, pre-scaled) into Ph, r_w_bias scaled ----
    {
        const __nv_bfloat16* Qg = g_Qh + ((size_t)(b * NH + n) * QLEN + i0) * DH;
#pragma unroll
        for (int e2 = 0; e2 < 2; e2++) {
            const int e = tid + e2 * 256;
            const int row = e >> 3, c4 = e & 7;     // 8 x 16B chunks per 64-bf16 row
            *(uint4*)((char*)Ph + row * (LH * 2) + c4 * 16) =
                *(const uint4*)(Qg + row * DH + c4 * 8);
        }
        if (tid < 64) Bws[tid] = r_w_bias[n * DH + tid] * SCALE_L2E;
    }

    // ---- prologue: cp.async stage 0 (jt = 0) ----
    {
        const int m0 = 1984 - i0;
#pragma unroll
        for (int e2 = 0; e2 < 8; e2++) {
            const int e = tid + e2 * 256;           // 2048 chunks
            const int row = e >> 3, c4 = e & 7;
            if (row < 64) {
                cp16(smb + SG_KR + row * (LH * 2) + c4 * 16, Kg0 + row * DH + c4 * 8, 16);
            } else if (row < 192) {
                const int rr = row - 64;
                const int m = m0 + rr;
                const uint32_t ok = (rr < 127 && m < QLEN) ? 16u : 0u;
                const __nv_bfloat16* src = Rg0 + (size_t)(ok ? m : 0) * DH + c4 * 8;
                cp16(smb + SG_KR + row * (LH * 2) + c4 * 16, src, ok);
            } else {
                const int d = row - 192;
                cp16(smb + SG_V + d * (LH * 2) + c4 * 16, Vt0 + (size_t)d * QLEN + c4 * 8, 16);
            }
        }
        CP_COMMIT();
        if (tid < 128) {
            const int m = m0 + tid;
            ((float*)(sm + SG_RB))[tid] =
                (tid < 127 && m < QLEN) ? r_bias[m * NH + n] * SCALE_L2E : 0.f;
        }
    }
    __syncthreads();

    // Q fragments -> registers (Ph reused for P afterwards)
    uint32_t af[4][4];
    {
        const int qr = wm * 16 + lq;
        const char* Pb = (char*)Ph;
#pragma unroll
        for (int kk = 0; kk < 4; kk++) {
            const int c0 = kk * 16 + 2 * lr;
            af[kk][0] = *(const uint32_t*)(Pb + (qr * LH + c0) * 2);
            af[kk][1] = *(const uint32_t*)(Pb + ((qr + 8) * LH + c0) * 2);
            af[kk][2] = *(const uint32_t*)(Pb + (qr * LH + c0 + 8) * 2);
            af[kk][3] = *(const uint32_t*)(Pb + ((qr + 8) * LH + c0 + 8) * 2);
        }
    }

    float oacc[4][4];
#pragma unroll
    for (int nt = 0; nt < 4; nt++)
#pragma unroll
        for (int u = 0; u < 4; u++) oacc[nt][u] = 0.f;

    const int srow = tid >> 2;
    const int q4 = tid & 3;
    float mi = NEGINF, li = 0.f;

    const int njt = it + 1;
    for (int jt = 0; jt < njt; jt++) {
        const bool diag = (jt == it);
        const char* SGc = sm + (jt & 1) * STAGE_BYTES;
        const char* KRb = SGc + SG_KR;
        const char* Vtb = SGc + SG_V;
        const float* Rbcur = (const float*)(SGc + SG_RB);

        CP_WAIT0();
        __syncthreads();

        // ---- prefetch stage jt+1 ----
        if (jt + 1 < njt) {
            const int j0n = (jt + 1) * 64;
            const int m0n = 1984 - i0 + j0n;
            const uint32_t nb = smb + ((jt + 1) & 1) * STAGE_BYTES;
            const __nv_bfloat16* Kgn = Kg0 + (size_t)j0n * DH;
#pragma unroll
            for (int e2 = 0; e2 < 8; e2++) {
                const int e = tid + e2 * 256;
                const int row = e >> 3, c4 = e & 7;
                if (row < 64) {
                    cp16(nb + SG_KR + row * (LH * 2) + c4 * 16, Kgn + row * DH + c4 * 8, 16);
                } else if (row < 192) {
                    const int rr = row - 64;
                    const int m = m0n + rr;
                    const uint32_t ok = (rr < 127 && m < QLEN) ? 16u : 0u;
                    const __nv_bfloat16* src = Rg0 + (size_t)(ok ? m : 0) * DH + c4 * 8;
                    cp16(nb + SG_KR + row * (LH * 2) + c4 * 16, src, ok);
                } else {
                    const int d = row - 192;
                    cp16(nb + SG_V + d * (LH * 2) + c4 * 16,
                         Vt0 + (size_t)d * QLEN + j0n + c4 * 8, 16);
                }
            }
            CP_COMMIT();
            if (tid < 128) {
                const int m = m0n + tid;
                ((float*)(sm + ((jt + 1) & 1) * STAGE_BYTES + SG_RB))[tid] =
                    (tid < 127 && m < QLEN) ? r_bias[m * NH + n] * SCALE_L2E : 0.f;
            }
        }

        // Bk[j] = (rwb*s) . k_j   (warps 0-1, overlaps mma of warps 2-7)
        if (tid < 64) {
            float s = 0.f;
            const __nv_bfloat162* krow = (const __nv_bfloat162*)(KRb + tid * (LH * 2));
#pragma unroll
            for (int dd = 0; dd < 32; dd++) {
                float2 kv = __bfloat1622float2(krow[dd]);
                s += Bws[dd * 2] * kv.x + Bws[dd * 2 + 1] * kv.y;
            }
            Bks[tid] = s;
        }

        // ---- ST = Q . KR^T  (64 x 192, bf16 k16) ----
        {
            float sacc[12][4];
#pragma unroll
            for (int nt = 0; nt < 12; nt++)
#pragma unroll
                for (int u = 0; u < 4; u++) sacc[nt][u] = 0.f;
#pragma unroll
            for (int kk = 0; kk < 4; kk++) {
                const int c0 = kk * 16 + 2 * lr;
                uint32_t bf[12][2];
#pragma unroll
                for (int nt = 0; nt < 12; nt++) {
                    const int bc = wn * 96 + nt * 8 + lq;
                    bf[nt][0] = *(const uint32_t*)(KRb + (bc * LH + c0) * 2);
                    bf[nt][1] = *(const uint32_t*)(KRb + (bc * LH + c0 + 8) * 2);
                }
#pragma unroll
                for (int nt = 0; nt < 12; nt++)
                    MMA_BF16(sacc[nt], af[kk], bf[nt]);
            }
            const int row0 = wm * 16 + lq;
#pragma unroll
            for (int nt = 0; nt < 12; nt++) {
                const int col = wn * 96 + nt * 8 + lr * 2;
                *(float2*)&STs[row0 * LST + col] = make_float2(sacc[nt][0], sacc[nt][1]);
                *(float2*)&STs[(row0 + 8) * LST + col] = make_float2(sacc[nt][2], sacc[nt][3]);
            }
        }
        __syncthreads();

        // ---- softmax (pre-scaled log2 domain, poly exp) ----
        {
            const int toff = 127 - srow;
            const int roff = 63 - srow;
            float z[16];
            float lmax = NEGINF;
#pragma unroll
            for (int c = 0; c < 16; c++) {
                const int jl = q4 + 4 * c;
                float s = STs[srow * LST + jl] + STs[srow * LST + toff + jl] +
                          Bks[jl] + Rbcur[roff + jl];
                if (diag && jl > srow) s = NEGINF;
                z[c] = s;
                lmax = fmaxf(lmax, s);
            }
            lmax = fmaxf(lmax, __shfl_xor_sync(0xffffffffu, lmax, 1));
            lmax = fmaxf(lmax, __shfl_xor_sync(0xffffffffu, lmax, 2));
            const float mnew = fmaxf(mi, lmax);
            const float csc = exp2_poly(mi - mnew);
            float lsum = 0.f;
#pragma unroll
            for (int c = 0; c < 16; c++) {
                const float p = exp2_poly(z[c] - mnew);
                Ph[srow * LH + q4 + 4 * c] = __float2bfloat16(p);
                lsum += p;
            }
            lsum += __shfl_xor_sync(0xffffffffu, lsum, 1);
            lsum += __shfl_xor_sync(0xffffffffu, lsum, 2);
            li = li * csc + lsum;
            mi = mnew;
            if (q4 == 0) cscs[srow] = csc;
        }
        __syncthreads();

        // ---- O = O*csc + P.V   (P bf16 [i][j], Vt bf16 [d][j]) ----
        {
            const int ar = wm * 16 + lq;
            const float c0 = cscs[ar];
            const float c1 = cscs[ar + 8];
#pragma unroll
            for (int nt = 0; nt < 4; nt++) {
                oacc[nt][0] *= c0; oacc[nt][1] *= c0;
                oacc[nt][2] *= c1; oacc[nt][3] *= c1;
            }
            const char* Pb = (char*)Ph;
#pragma unroll
            for (int kk = 0; kk < 4; kk++) {
                const int c0k = kk * 16 + 2 * lr;
                uint32_t pa[4];
                pa[0] = *(const uint32_t*)(Pb + (ar * LH + c0k) * 2);
                pa[1] = *(const uint32_t*)(Pb + ((ar + 8) * LH + c0k) * 2);
                pa[2] = *(const uint32_t*)(Pb + (ar * LH + c0k + 8) * 2);
                pa[3] = *(const uint32_t*)(Pb + ((ar + 8) * LH + c0k + 8) * 2);
#pragma unroll
                for (int nt = 0; nt < 4; nt++) {
                    const int d = wn * 32 + nt * 8 + lq;
                    uint32_t vb[2];
                    vb[0] = *(const uint32_t*)(Vtb + (d * LH + c0k) * 2);
                    vb[1] = *(const uint32_t*)(Vtb + (d * LH + c0k + 8) * 2);
                    MMA_BF16(oacc[nt], pa, vb);
                }
            }
        }
    }

    // ---- epilogue ----
    if (q4 == 0) lis[srow] = li;
    __syncthreads();
    {
        const int r0 = wm * 16 + lq;
        const float inv0 = 1.f / lis[r0];
        const float inv1 = 1.f / lis[r0 + 8];
#pragma unroll
        for (int nt = 0; nt < 4; nt++) {
            const int d = wn * 32 + nt * 8 + lr * 2;
            float* p0 = g_att + ((size_t)(i0 + r0) * BSZ + b) * DM + n * DH + d;
            *(float2*)p0 = make_float2(oacc[nt][0] * inv0, oacc[nt][1] * inv0);
            float* p1 = g_att + ((size_t)(i0 + r0 + 8) * BSZ + b) * DM + n * DH + d;
            *(float2*)p1 = make_float2(oacc[nt][2] * inv1, oacc[nt][3] * inv1);
        }
    }
}

// ================= Kernel 4: LayerNorm ========================================
__device__ __forceinline__ float block_sum(float v, float* red) {
#pragma unroll
    for (int o = 16; o > 0; o >>= 1) v += __shfl_xor_sync(0xffffffffu, v, o);
    const int w = threadIdx.x >> 5;
    if ((threadIdx.x & 31) == 0) red[w] = v;
    __syncthreads();
    if (threadIdx.x < 32) {
        float t = (threadIdx.x < 8) ? red[threadIdx.x] : 0.f;
#pragma unroll
        for (int o = 4; o > 0; o >>= 1) t += __shfl_xor_sync(0xffffffffu, t, o);
        if (threadIdx.x == 0) red[0] = t;
    }
    __syncthreads();
    const float r = red[0];
    __syncthreads();
    return r;
}

__global__ void __launch_bounds__(256) ln_kernel(const float* __restrict__ gamma,
                                                 const float* __restrict__ beta,
                                                 float* __restrict__ out) {
    __shared__ float red[8];
    const int r = blockIdx.x;
    const float* x = g_res + (size_t)r * DM;
    const int tid = threadIdx.x;
    float v[3];
#pragma unroll
    for (int u = 0; u < 3; u++) v[u] = x[tid + u * 256];
    const float total = block_sum(v[0] + v[1] + v[2], red);
    const float mu = total * (1.f / DM);
    float sq = 0.f;
#pragma unroll
    for (int u = 0; u < 3; u++) { const float d = v[u] - mu; sq += d * d; }
    const float var = block_sum(sq, red) * (1.f / DM);
    const float inv = rsqrtf(var + 1e-5f);
#pragma unroll
    for (int u = 0; u < 3; u++) {
        const int c = tid + u * 256;
        out[(size_t)r * DM + c] = (v[u] - mu) * inv * gamma[c] + beta[c];
    }
}

// ================= launch =====================================================
extern "C" void kernel_launch(void* const* d_in, const int* in_sizes, int n_in,
                              void* d_out, int out_size) {
    const float* w        = (const float*)d_in[0];
    const float* r_emb    = (const float*)d_in[1];
    const float* r_w_bias = (const float*)d_in[2];
    const float* r_bias   = (const float*)d_in[3];
    const float* qkv_w    = (const float*)d_in[4];
    const float* o_w      = (const float*)d_in[5];
    const float* ln_g     = (const float*)d_in[6];
    const float* ln_b     = (const float*)d_in[7];
    float* out = (float*)d_out;

    float* g_att_ptr = nullptr;
    cudaGetSymbolAddress((void**)&g_att_ptr, g_att);

    conv_r_kernel<<<QLEN, 256>>>(r_emb);

    // QKV projection -> bf16 Q/K/Vt
    mma_gemm_kernel<0><<<dim3(QLEN * BSZ / BM, 3 * DM / BN), 256>>>(w, qkv_w, nullptr, DM);

    // bf16 pipelined flash rel-attention
    (void)cudaFuncSetAttribute(attn_kernel, cudaFuncAttributeMaxDynamicSharedMemorySize,
                               ATTN_SMEM_BYTES);
    attn_kernel<<<dim3(QLEN / 64, BSZ * NH), 256, ATTN_SMEM_BYTES>>>(r_bias, r_w_bias);

    // O-projection + residual
    mma_gemm_kernel<1><<<dim3(QLEN * BSZ / BM, DM / BN), 256>>>(g_att_ptr, o_w, w, DM);

    ln_kernel<<<QLEN * BSZ, 256>>>(ln_g, ln_b, out);
}

// round 9
// speedup vs baseline: 4.2521x; 1.0469x over previous
#include <cuda_runtime.h>
#include <cuda_bf16.h>
#include <cstdint>

#define QLEN 2048
#define BSZ 2
#define NH 12
#define DH 64
#define DM 768
#define NEGINF (-1e30f)
#define SCALE_L2E 0.1803368801111244f     // (1/sqrt(64)) * log2(e)

// ---------------- scratch (static device allocations) --------------------------
__device__ __nv_bfloat16 g_Qh[BSZ * NH * QLEN * DH];   // [b][n][i][d], pre-scaled by SCALE_L2E
__device__ __nv_bfloat16 g_Kh[BSZ * NH * QLEN * DH];   // [b][n][j][d]
__device__ __nv_bfloat16 g_Vt[BSZ * NH * DH * QLEN];   // [b][n][d][j]  (transposed)
__device__ __nv_bfloat16 g_Rh[NH * QLEN * DH];         // [n][m][d]
__device__ float g_att[QLEN * BSZ * DM];               // attn_vec, row r = i*BSZ+b
__device__ float g_res[QLEN * BSZ * DM];               // w + attn_out

__device__ __forceinline__ uint32_t smem_u32(const void* p) {
    uint32_t a;
    asm("{ .reg .u64 t; cvta.to.shared.u64 t, %1; cvt.u32.u64 %0, t; }" : "=r"(a) : "l"(p));
    return a;
}
__device__ __forceinline__ void cp16(uint32_t dst, const void* src, uint32_t srcsize) {
    asm volatile("cp.async.cg.shared.global [%0], [%1], 16, %2;"
                 :: "r"(dst), "l"(src), "r"(srcsize) : "memory");
}
#define CP_COMMIT() asm volatile("cp.async.commit_group;" ::: "memory")
#define CP_WAIT0()  asm volatile("cp.async.wait_group 0;" ::: "memory")

#define MMA_TF32(d, a, b)                                                          \
    asm volatile("mma.sync.aligned.m16n8k8.row.col.f32.tf32.tf32.f32 "             \
                 "{%0,%1,%2,%3}, {%4,%5,%6,%7}, {%8,%9}, {%0,%1,%2,%3};"           \
                 : "+f"((d)[0]), "+f"((d)[1]), "+f"((d)[2]), "+f"((d)[3])          \
                 : "r"((a)[0]), "r"((a)[1]), "r"((a)[2]), "r"((a)[3]),             \
                   "r"((b)[0]), "r"((b)[1]))

#define MMA_BF16(d, a, b)                                                          \
    asm volatile("mma.sync.aligned.m16n8k16.row.col.f32.bf16.bf16.f32 "            \
                 "{%0,%1,%2,%3}, {%4,%5,%6,%7}, {%8,%9}, {%0,%1,%2,%3};"           \
                 : "+f"((d)[0]), "+f"((d)[1]), "+f"((d)[2]), "+f"((d)[3])          \
                 : "r"((a)[0]), "r"((a)[1]), "r"((a)[2]), "r"((a)[3]),             \
                   "r"((b)[0]), "r"((b)[1]))

// fast 2^t for t <= 0 (clamped); deg-4 Taylor in f*ln2; rel err <= ~9e-5
__device__ __forceinline__ float exp2_poly(float t) {
    t = fmaxf(t, -100.f);
    const float r = rintf(t);
    const float y = (t - r) * 0.6931471805599453f;
    float p = 0.041666667f;
    p = p * y + 0.166666667f;
    p = p * y + 0.5f;
    p = p * y + 1.0f;
    p = p * y + 1.0f;
    const int ri = (int)r;
    return p * __int_as_float((ri + 127) << 23);
}

// ================= cp.async-pipelined tf32 projection GEMM =====================
// C[r, c] = sum_k A[r, k] * B[c, k]  (both K-major, .row.col mma, raw fp32 -> HW tf32)
// MODE 0: scatter bf16 into g_Qh (pre-scaled) / g_Kh / g_Vt.  MODE 1: +W -> g_res.
#define BM 128
#define BN 128
#define BKC 32
#define PLDP 36
#define PSTAGE_FLOATS (2 * BM * PLDP)        // A + B = 9216 floats = 36864 B
#define PROJ_SMEM_BYTES (2 * PSTAGE_FLOATS * 4)   // 73728 B

template <int MODE>
__global__ void __launch_bounds__(256) mma_gemm_kernel(const float* __restrict__ A,
                                                       const float* __restrict__ B,
                                                       const float* __restrict__ W,
                                                       int kdim) {
    extern __shared__ float psm[];
    const uint32_t smb = smem_u32(psm);

    const int tid = threadIdx.x;
    const int wid = tid >> 5, lane = tid & 31;
    const int wm = wid & 3;
    const int wn = wid >> 2;
    const int rb = blockIdx.x * BM;
    const int cb = blockIdx.y * BN;
    const int lq = lane >> 2;
    const int lr = lane & 3;

    const int nchunk = kdim / BKC;

    // issue cp.async fill of stage s for K-chunk c
    auto issue = [&](int c, int s) {
        const int k0 = c * BKC;
        const uint32_t sb = smb + (uint32_t)s * PSTAGE_FLOATS * 4;
#pragma unroll
        for (int e2 = 0; e2 < 8; e2++) {
            const int e = tid + e2 * 256;          // 0..2047
            const int row = (e & 1023) >> 3, c4 = e & 7;
            if (e < 1024) {
                cp16(sb + (uint32_t)(row * PLDP + c4 * 4) * 4,
                     A + (size_t)(rb + row) * kdim + k0 + c4 * 4, 16);
            } else {
                cp16(sb + (uint32_t)((BM + row) * PLDP + c4 * 4) * 4,
                     B + (size_t)(cb + row) * kdim + k0 + c4 * 4, 16);
            }
        }
        CP_COMMIT();
    };

    float acc[2][8][4];
#pragma unroll
    for (int mt = 0; mt < 2; mt++)
#pragma unroll
        for (int nt = 0; nt < 8; nt++)
#pragma unroll
            for (int u = 0; u < 4; u++) acc[mt][nt][u] = 0.f;

    issue(0, 0);
    for (int c = 0; c < nchunk; c++) {
        CP_WAIT0();
        __syncthreads();
        if (c + 1 < nchunk) issue(c + 1, (c + 1) & 1);

        const float* As = psm + (c & 1) * PSTAGE_FLOATS;
        const float* Bs = As + BM * PLDP;
#pragma unroll
        for (int kk = 0; kk < BKC / 8; kk++) {
            const int k = kk * 8;
            uint32_t af[2][4];
#pragma unroll
            for (int mt = 0; mt < 2; mt++) {
                const int ar = wm * 32 + mt * 16 + lq;
                af[mt][0] = __float_as_uint(As[ar * PLDP + k + lr]);
                af[mt][1] = __float_as_uint(As[(ar + 8) * PLDP + k + lr]);
                af[mt][2] = __float_as_uint(As[ar * PLDP + k + 4 + lr]);
                af[mt][3] = __float_as_uint(As[(ar + 8) * PLDP + k + 4 + lr]);
            }
            uint32_t bf[8][2];
#pragma unroll
            for (int nt = 0; nt < 8; nt++) {
                const int bc = wn * 64 + nt * 8 + lq;
                bf[nt][0] = __float_as_uint(Bs[bc * PLDP + k + lr]);
                bf[nt][1] = __float_as_uint(Bs[bc * PLDP + k + 4 + lr]);
            }
#pragma unroll
            for (int mt = 0; mt < 2; mt++)
#pragma unroll
                for (int nt = 0; nt < 8; nt++)
                    MMA_TF32(acc[mt][nt], af[mt], bf[nt]);
        }
        __syncthreads();
    }

#pragma unroll
    for (int mt = 0; mt < 2; mt++) {
#pragma unroll
        for (int half = 0; half < 2; half++) {
            const int r = rb + wm * 32 + mt * 16 + lq + half * 8;
#pragma unroll
            for (int nt = 0; nt < 8; nt++) {
                const int h = cb + wn * 64 + nt * 8 + lr * 2;
                const float v0 = acc[mt][nt][half * 2 + 0];
                const float v1 = acc[mt][nt][half * 2 + 1];
                if (MODE == 0) {
                    const int i = r >> 1, b = r & 1;
                    const int sel = h / DM;
                    const int rem = h - sel * DM;
                    const int n = rem >> 6, d0 = rem & 63;
                    if (sel == 0) {
                        __nv_bfloat162 p = __floats2bfloat162_rn(v0 * SCALE_L2E, v1 * SCALE_L2E);
                        *(__nv_bfloat162*)(g_Qh + ((size_t)(b * NH + n) * QLEN + i) * DH + d0) = p;
                    } else if (sel == 1) {
                        __nv_bfloat162 p = __floats2bfloat162_rn(v0, v1);
                        *(__nv_bfloat162*)(g_Kh + ((size_t)(b * NH + n) * QLEN + i) * DH + d0) = p;
                    } else {
                        g_Vt[((size_t)(b * NH + n) * DH + d0) * QLEN + i] = __float2bfloat16(v0);
                        g_Vt[((size_t)(b * NH + n) * DH + d0 + 1) * QLEN + i] = __float2bfloat16(v1);
                    }
                } else {
                    const float2 wv = *(const float2*)(W + (size_t)r * DM + h);
                    *(float2*)(g_res + (size_t)r * DM + h) =
                        make_float2(v0 + wv.x, v1 + wv.y);
                }
            }
        }
    }
}

// ================= r_emb -> bf16 head-major ===================================
__global__ void __launch_bounds__(256) conv_r_kernel(const float* __restrict__ r_emb) {
    const int m = blockIdx.x;
    const int tid = threadIdx.x;
#pragma unroll
    for (int u = 0; u < 3; u++) {
        const int e = tid + u * 256;            // 0..767
        const int n = e >> 6, d = e & 63;
        g_Rh[((size_t)n * QLEN + m) * DH + d] =
            __float2bfloat16(r_emb[(size_t)m * NH * DH + e]);
    }
}

// ================= Kernel 2: bf16 cp.async-pipelined flash rel-attention =======
#define LH 72                                 // bf16 row stride (144 B)
#define LST 196                               // fp32 score row stride
// stage layout (bytes): KR[192][72 bf16] | Vt[64][72 bf16] | Rb[128 f32]
#define SG_KR 0
#define SG_V  (192 * LH * 2)                  // 27648
#define SG_RB (SG_V + 64 * LH * 2)            // 36864
#define STAGE_BYTES (SG_RB + 128 * 4)         // 37376
// full smem (bytes)
#define OF_ST  (2 * STAGE_BYTES)              // 74752 : STs fp32 64x196
#define OF_PQ  (OF_ST + 64 * LST * 4)         // 124928 : P/Q bf16 64x72
#define OF_BW  (OF_PQ + 64 * LH * 2)          // 134144
#define OF_BK  (OF_BW + 256)
#define OF_CSC (OF_BK + 256)
#define OF_LI  (OF_CSC + 256)
#define ATTN_SMEM_BYTES (OF_LI + 256)         // 135168

__global__ void __launch_bounds__(256, 1) attn_kernel(const float* __restrict__ r_bias,
                                                      const float* __restrict__ r_w_bias) {
    extern __shared__ char sm[];
    const uint32_t smb = smem_u32(sm);
    float* STs = (float*)(sm + OF_ST);
    __nv_bfloat16* Ph = (__nv_bfloat16*)(sm + OF_PQ);
    float* Bws = (float*)(sm + OF_BW);
    float* Bks = (float*)(sm + OF_BK);
    float* cscs = (float*)(sm + OF_CSC);
    float* lis  = (float*)(sm + OF_LI);

    const int bn = blockIdx.y;
    const int b = bn / NH, n = bn % NH;
    const int it = (gridDim.x - 1) - blockIdx.x;   // longest blocks first
    const int i0 = it * 64;
    const int tid = threadIdx.x;
    const int wid = tid >> 5, lane = tid & 31;
    const int wm = wid & 3;
    const int wn = wid >> 2;
    const int lq = lane >> 2, lr = lane & 3;

    const __nv_bfloat16* Kg0 = g_Kh + (size_t)(b * NH + n) * QLEN * DH;
    const __nv_bfloat16* Vt0 = g_Vt + (size_t)(b * NH + n) * DH * QLEN;
    const __nv_bfloat16* Rg0 = g_Rh + (size_t)n * QLEN * DH;

    // ---- prologue: Q tile (bf16, pre-scaled) into Ph, r_w_bias scaled ----
    {
        const __nv_bfloat16* Qg = g_Qh + ((size_t)(b * NH + n) * QLEN + i0) * DH;
#pragma unroll
        for (int e2 = 0; e2 < 2; e2++) {
            const int e = tid + e2 * 256;
            const int row = e >> 3, c4 = e & 7;     // 8 x 16B chunks per 64-bf16 row
            *(uint4*)((char*)Ph + row * (LH * 2) + c4 * 16) =
                *(const uint4*)(Qg + row * DH + c4 * 8);
        }
        if (tid < 64) Bws[tid] = r_w_bias[n * DH + tid] * SCALE_L2E;
    }

    // ---- prologue: cp.async stage 0 (jt = 0) ----
    {
        const int m0 = 1984 - i0;
#pragma unroll
        for (int e2 = 0; e2 < 8; e2++) {
            const int e = tid + e2 * 256;           // 2048 chunks
            const int row = e >> 3, c4 = e & 7;
            if (row < 64) {
                cp16(smb + SG_KR + row * (LH * 2) + c4 * 16, Kg0 + row * DH + c4 * 8, 16);
            } else if (row < 192) {
                const int rr = row - 64;
                const int m = m0 + rr;
                const uint32_t ok = (rr < 127 && m < QLEN) ? 16u : 0u;
                const __nv_bfloat16* src = Rg0 + (size_t)(ok ? m : 0) * DH + c4 * 8;
                cp16(smb + SG_KR + row * (LH * 2) + c4 * 16, src, ok);
            } else {
                const int d = row - 192;
                cp16(smb + SG_V + d * (LH * 2) + c4 * 16, Vt0 + (size_t)d * QLEN + c4 * 8, 16);
            }
        }
        CP_COMMIT();
        if (tid < 128) {
            const int m = m0 + tid;
            ((float*)(sm + SG_RB))[tid] =
                (tid < 127 && m < QLEN) ? r_bias[m * NH + n] * SCALE_L2E : 0.f;
        }
    }
    __syncthreads();

    // Q fragments -> registers (Ph reused for P afterwards)
    uint32_t af[4][4];
    {
        const int qr = wm * 16 + lq;
        const char* Pb = (char*)Ph;
#pragma unroll
        for (int kk = 0; kk < 4; kk++) {
            const int c0 = kk * 16 + 2 * lr;
            af[kk][0] = *(const uint32_t*)(Pb + (qr * LH + c0) * 2);
            af[kk][1] = *(const uint32_t*)(Pb + ((qr + 8) * LH + c0) * 2);
            af[kk][2] = *(const uint32_t*)(Pb + (qr * LH + c0 + 8) * 2);
            af[kk][3] = *(const uint32_t*)(Pb + ((qr + 8) * LH + c0 + 8) * 2);
        }
    }

    float oacc[4][4];
#pragma unroll
    for (int nt = 0; nt < 4; nt++)
#pragma unroll
        for (int u = 0; u < 4; u++) oacc[nt][u] = 0.f;

    const int srow = tid >> 2;
    const int q4 = tid & 3;
    float mi = NEGINF, li = 0.f;

    const int njt = it + 1;
    for (int jt = 0; jt < njt; jt++) {
        const bool diag = (jt == it);
        const char* SGc = sm + (jt & 1) * STAGE_BYTES;
        const char* KRb = SGc + SG_KR;
        const char* Vtb = SGc + SG_V;
        const float* Rbcur = (const float*)(SGc + SG_RB);

        CP_WAIT0();
        __syncthreads();

        // ---- prefetch stage jt+1 ----
        if (jt + 1 < njt) {
            const int j0n = (jt + 1) * 64;
            const int m0n = 1984 - i0 + j0n;
            const uint32_t nb = smb + ((jt + 1) & 1) * STAGE_BYTES;
            const __nv_bfloat16* Kgn = Kg0 + (size_t)j0n * DH;
#pragma unroll
            for (int e2 = 0; e2 < 8; e2++) {
                const int e = tid + e2 * 256;
                const int row = e >> 3, c4 = e & 7;
                if (row < 64) {
                    cp16(nb + SG_KR + row * (LH * 2) + c4 * 16, Kgn + row * DH + c4 * 8, 16);
                } else if (row < 192) {
                    const int rr = row - 64;
                    const int m = m0n + rr;
                    const uint32_t ok = (rr < 127 && m < QLEN) ? 16u : 0u;
                    const __nv_bfloat16* src = Rg0 + (size_t)(ok ? m : 0) * DH + c4 * 8;
                    cp16(nb + SG_KR + row * (LH * 2) + c4 * 16, src, ok);
                } else {
                    const int d = row - 192;
                    cp16(nb + SG_V + d * (LH * 2) + c4 * 16,
                         Vt0 + (size_t)d * QLEN + j0n + c4 * 8, 16);
                }
            }
            CP_COMMIT();
            if (tid < 128) {
                const int m = m0n + tid;
                ((float*)(sm + ((jt + 1) & 1) * STAGE_BYTES + SG_RB))[tid] =
                    (tid < 127 && m < QLEN) ? r_bias[m * NH + n] * SCALE_L2E : 0.f;
            }
        }

        // Bk[j] = (rwb*s) . k_j   (warps 0-1, overlaps mma of warps 2-7)
        if (tid < 64) {
            float s = 0.f;
            const __nv_bfloat162* krow = (const __nv_bfloat162*)(KRb + tid * (LH * 2));
#pragma unroll
            for (int dd = 0; dd < 32; dd++) {
                float2 kv = __bfloat1622float2(krow[dd]);
                s += Bws[dd * 2] * kv.x + Bws[dd * 2 + 1] * kv.y;
            }
            Bks[tid] = s;
        }

        // ---- ST = Q . KR^T  (64 x 192, bf16 k16) ----
        {
            float sacc[12][4];
#pragma unroll
            for (int nt = 0; nt < 12; nt++)
#pragma unroll
                for (int u = 0; u < 4; u++) sacc[nt][u] = 0.f;
#pragma unroll
            for (int kk = 0; kk < 4; kk++) {
                const int c0 = kk * 16 + 2 * lr;
                uint32_t bf[12][2];
#pragma unroll
                for (int nt = 0; nt < 12; nt++) {
                    const int bc = wn * 96 + nt * 8 + lq;
                    bf[nt][0] = *(const uint32_t*)(KRb + (bc * LH + c0) * 2);
                    bf[nt][1] = *(const uint32_t*)(KRb + (bc * LH + c0 + 8) * 2);
                }
#pragma unroll
                for (int nt = 0; nt < 12; nt++)
                    MMA_BF16(sacc[nt], af[kk], bf[nt]);
            }
            const int row0 = wm * 16 + lq;
#pragma unroll
            for (int nt = 0; nt < 12; nt++) {
                const int col = wn * 96 + nt * 8 + lr * 2;
                *(float2*)&STs[row0 * LST + col] = make_float2(sacc[nt][0], sacc[nt][1]);
                *(float2*)&STs[(row0 + 8) * LST + col] = make_float2(sacc[nt][2], sacc[nt][3]);
            }
        }
        __syncthreads();

        // ---- softmax (pre-scaled log2 domain, poly exp) ----
        {
            const int toff = 127 - srow;
            const int roff = 63 - srow;
            float z[16];
            float lmax = NEGINF;
#pragma unroll
            for (int c = 0; c < 16; c++) {
                const int jl = q4 + 4 * c;
                float s = STs[srow * LST + jl] + STs[srow * LST + toff + jl] +
                          Bks[jl] + Rbcur[roff + jl];
                if (diag && jl > srow) s = NEGINF;
                z[c] = s;
                lmax = fmaxf(lmax, s);
            }
            lmax = fmaxf(lmax, __shfl_xor_sync(0xffffffffu, lmax, 1));
            lmax = fmaxf(lmax, __shfl_xor_sync(0xffffffffu, lmax, 2));
            const float mnew = fmaxf(mi, lmax);
            const float csc = exp2_poly(mi - mnew);
            float lsum = 0.f;
#pragma unroll
            for (int c = 0; c < 16; c++) {
                const float p = exp2_poly(z[c] - mnew);
                Ph[srow * LH + q4 + 4 * c] = __float2bfloat16(p);
                lsum += p;
            }
            lsum += __shfl_xor_sync(0xffffffffu, lsum, 1);
            lsum += __shfl_xor_sync(0xffffffffu, lsum, 2);
            li = li * csc + lsum;
            mi = mnew;
            if (q4 == 0) cscs[srow] = csc;
        }
        __syncthreads();

        // ---- O = O*csc + P.V   (P bf16 [i][j], Vt bf16 [d][j]) ----
        {
            const int ar = wm * 16 + lq;
            const float c0 = cscs[ar];
            const float c1 = cscs[ar + 8];
#pragma unroll
            for (int nt = 0; nt < 4; nt++) {
                oacc[nt][0] *= c0; oacc[nt][1] *= c0;
                oacc[nt][2] *= c1; oacc[nt][3] *= c1;
            }
            const char* Pb = (char*)Ph;
#pragma unroll
            for (int kk = 0; kk < 4; kk++) {
                const int c0k = kk * 16 + 2 * lr;
                uint32_t pa[4];
                pa[0] = *(const uint32_t*)(Pb + (ar * LH + c0k) * 2);
                pa[1] = *(const uint32_t*)(Pb + ((ar + 8) * LH + c0k) * 2);
                pa[2] = *(const uint32_t*)(Pb + (ar * LH + c0k + 8) * 2);
                pa[3] = *(const uint32_t*)(Pb + ((ar + 8) * LH + c0k + 8) * 2);
#pragma unroll
                for (int nt = 0; nt < 4; nt++) {
                    const int d = wn * 32 + nt * 8 + lq;
                    uint32_t vb[2];
                    vb[0] = *(const uint32_t*)(Vtb + (d * LH + c0k) * 2);
                    vb[1] = *(const uint32_t*)(Vtb + (d * LH + c0k + 8) * 2);
                    MMA_BF16(oacc[nt], pa, vb);
                }
            }
        }
    }

    // ---- epilogue ----
    if (q4 == 0) lis[srow] = li;
    __syncthreads();
    {
        const int r0 = wm * 16 + lq;
        const float inv0 = 1.f / lis[r0];
        const float inv1 = 1.f / lis[r0 + 8];
#pragma unroll
        for (int nt = 0; nt < 4; nt++) {
            const int d = wn * 32 + nt * 8 + lr * 2;
            float* p0 = g_att + ((size_t)(i0 + r0) * BSZ + b) * DM + n * DH + d;
            *(float2*)p0 = make_float2(oacc[nt][0] * inv0, oacc[nt][1] * inv0);
            float* p1 = g_att + ((size_t)(i0 + r0 + 8) * BSZ + b) * DM + n * DH + d;
            *(float2*)p1 = make_float2(oacc[nt][2] * inv1, oacc[nt][3] * inv1);
        }
    }
}

// ================= Kernel 4: LayerNorm ========================================
__device__ __forceinline__ float block_sum(float v, float* red) {
#pragma unroll
    for (int o = 16; o > 0; o >>= 1) v += __shfl_xor_sync(0xffffffffu, v, o);
    const int w = threadIdx.x >> 5;
    if ((threadIdx.x & 31) == 0) red[w] = v;
    __syncthreads();
    if (threadIdx.x < 32) {
        float t = (threadIdx.x < 8) ? red[threadIdx.x] : 0.f;
#pragma unroll
        for (int o = 4; o > 0; o >>= 1) t += __shfl_xor_sync(0xffffffffu, t, o);
        if (threadIdx.x == 0) red[0] = t;
    }
    __syncthreads();
    const float r = red[0];
    __syncthreads();
    return r;
}

__global__ void __launch_bounds__(256) ln_kernel(const float* __restrict__ gamma,
                                                 const float* __restrict__ beta,
                                                 float* __restrict__ out) {
    __shared__ float red[8];
    const int r = blockIdx.x;
    const float* x = g_res + (size_t)r * DM;
    const int tid = threadIdx.x;
    float v[3];
#pragma unroll
    for (int u = 0; u < 3; u++) v[u] = x[tid + u * 256];
    const float total = block_sum(v[0] + v[1] + v[2], red);
    const float mu = total * (1.f / DM);
    float sq = 0.f;
#pragma unroll
    for (int u = 0; u < 3; u++) { const float d = v[u] - mu; sq += d * d; }
    const float var = block_sum(sq, red) * (1.f / DM);
    const float inv = rsqrtf(var + 1e-5f);
#pragma unroll
    for (int u = 0; u < 3; u++) {
        const int c = tid + u * 256;
        out[(size_t)r * DM + c] = (v[u] - mu) * inv * gamma[c] + beta[c];
    }
}

// ================= launch =====================================================
extern "C" void kernel_launch(void* const* d_in, const int* in_sizes, int n_in,
                              void* d_out, int out_size) {
    const float* w        = (const float*)d_in[0];
    const float* r_emb    = (const float*)d_in[1];
    const float* r_w_bias = (const float*)d_in[2];
    const float* r_bias   = (const float*)d_in[3];
    const float* qkv_w    = (const float*)d_in[4];
    const float* o_w      = (const float*)d_in[5];
    const float* ln_g     = (const float*)d_in[6];
    const float* ln_b     = (const float*)d_in[7];
    float* out = (float*)d_out;

    float* g_att_ptr = nullptr;
    cudaGetSymbolAddress((void**)&g_att_ptr, g_att);

    conv_r_kernel<<<QLEN, 256>>>(r_emb);

    (void)cudaFuncSetAttribute(mma_gemm_kernel<0>,
                               cudaFuncAttributeMaxDynamicSharedMemorySize, PROJ_SMEM_BYTES);
    (void)cudaFuncSetAttribute(mma_gemm_kernel<1>,
                               cudaFuncAttributeMaxDynamicSharedMemorySize, PROJ_SMEM_BYTES);

    // QKV projection -> bf16 Q/K/Vt
    mma_gemm_kernel<0><<<dim3(QLEN * BSZ / BM, 3 * DM / BN), 256, PROJ_SMEM_BYTES>>>(
        w, qkv_w, nullptr, DM);

    // bf16 pipelined flash rel-attention
    (void)cudaFuncSetAttribute(attn_kernel, cudaFuncAttributeMaxDynamicSharedMemorySize,
                               ATTN_SMEM_BYTES);
    attn_kernel<<<dim3(QLEN / 64, BSZ * NH), 256, ATTN_SMEM_BYTES>>>(r_bias, r_w_bias);

    // O-projection + residual
    mma_gemm_kernel<1><<<dim3(QLEN * BSZ / BM, DM / BN), 256, PROJ_SMEM_BYTES>>>(
        g_att_ptr, o_w, w, DM);

    ln_kernel<<<QLEN * BSZ, 256>>>(ln_g, ln_b, out);
}